// round 1
// baseline (speedup 1.0000x reference)
#include <cuda_runtime.h>
#include <math.h>

// ---------------------------------------------------------------------------
// Problem constants
// ---------------------------------------------------------------------------
#define N_NODES 100000
#define F_IN    256
#define HID     128
#define CLS     32
#define EPS_F   0.1f
#define GAMMA_F 0.1f

// ---------------------------------------------------------------------------
// Scratch (device globals -- no allocation allowed)
// ---------------------------------------------------------------------------
__device__ __align__(16) float g_deg [N_NODES];
__device__ __align__(16) float g_dinv[N_NODES];
__device__ __align__(16) float g_h1  [(size_t)N_NODES * HID];        // 51.2 MB
__device__ __align__(16) float g_t1  [(size_t)N_NODES * (2 * HID)];  // 102.4 MB (xw1 | z1)
__device__ __align__(16) float g_agg1[(size_t)N_NODES * HID];        // 51.2 MB
__device__ __align__(16) float g_h2  [(size_t)N_NODES * CLS];        // 12.8 MB
__device__ __align__(16) float g_t2  [(size_t)N_NODES * (2 * CLS)];  // 25.6 MB (xw2 | z2)
__device__ __align__(16) float g_agg2[(size_t)N_NODES * CLS];        // 12.8 MB
__device__ __align__(16) float g_comb1[2 * HID * HID];
__device__ __align__(16) float g_comb2[2 * CLS * CLS];

// ---------------------------------------------------------------------------
// Degree / normalization
// ---------------------------------------------------------------------------
__global__ void k_deg_init() {
    int i = blockIdx.x * blockDim.x + threadIdx.x;
    if (i < N_NODES) g_deg[i] = 1.0f;  // self loop
}

__global__ void k_deg_accum(const int* __restrict__ col, int E) {
    int e = blockIdx.x * blockDim.x + threadIdx.x;
    if (e < E) atomicAdd(&g_deg[col[e]], 1.0f);
}

__global__ void k_dinv() {
    int i = blockIdx.x * blockDim.x + threadIdx.x;
    if (i < N_NODES) g_dinv[i] = rsqrtf(g_deg[i]);
}

// ---------------------------------------------------------------------------
// Combined weight build: rows [0,d)   = phi_w
//                        rows [d,2d)  = W - W^T - gamma*I
// ---------------------------------------------------------------------------
__global__ void k_comb(const float* __restrict__ W, const float* __restrict__ phi,
                       float* __restrict__ comb, int d) {
    int i = blockIdx.x * blockDim.x + threadIdx.x;
    if (i >= d * d) return;
    int r = i / d, c = i % d;
    comb[r * d + c] = phi[i];
    float aw = W[r * d + c] - W[c * d + r] - ((r == c) ? GAMMA_F : 0.0f);
    comb[(d + r) * d + c] = aw;
}

// ---------------------------------------------------------------------------
// Register-tiled fp32 GEMM:  C[M,Ncols] = A[M,K] @ B[Ncols,K]^T (+bias)(+relu)
// ---------------------------------------------------------------------------
template<int BM, int BN, int BK, int TM, int TN, bool RELU, bool HASB>
__global__ void k_gemm(const float* __restrict__ A, const float* __restrict__ B,
                       const float* __restrict__ bias, float* __restrict__ C,
                       int M, int Ncols, int K) {
    constexpr int THREADS = (BM / TM) * (BN / TN);
    __shared__ float As[BM][BK + 1];
    __shared__ float Bs[BK][BN + 1];

    int tid  = threadIdx.x;
    int tcol = tid % (BN / TN);
    int trow = tid / (BN / TN);
    int row0 = blockIdx.y * BM;
    int col0 = blockIdx.x * BN;

    float acc[TM][TN];
#pragma unroll
    for (int i = 0; i < TM; i++)
#pragma unroll
        for (int j = 0; j < TN; j++) acc[i][j] = 0.0f;

    for (int k0 = 0; k0 < K; k0 += BK) {
#pragma unroll
        for (int i = tid; i < BM * BK; i += THREADS) {
            int r = i / BK, c = i % BK;
            int gr = row0 + r;
            As[r][c] = (gr < M) ? A[(long)gr * K + k0 + c] : 0.0f;
        }
#pragma unroll
        for (int i = tid; i < BN * BK; i += THREADS) {
            int r = i / BK, c = i % BK;
            Bs[c][r] = B[(long)(col0 + r) * K + k0 + c];
        }
        __syncthreads();

#pragma unroll
        for (int k = 0; k < BK; k++) {
            float ra[TM], rb[TN];
#pragma unroll
            for (int i = 0; i < TM; i++) ra[i] = As[trow * TM + i][k];
#pragma unroll
            for (int j = 0; j < TN; j++) rb[j] = Bs[k][tcol * TN + j];
#pragma unroll
            for (int i = 0; i < TM; i++)
#pragma unroll
                for (int j = 0; j < TN; j++)
                    acc[i][j] = fmaf(ra[i], rb[j], acc[i][j]);
        }
        __syncthreads();
    }

#pragma unroll
    for (int i = 0; i < TM; i++) {
        int gr = row0 + trow * TM + i;
        if (gr >= M) continue;
#pragma unroll
        for (int j = 0; j < TN; j++) {
            int gc = col0 + tcol * TN + j;
            float v = acc[i][j];
            if (HASB) v += bias[gc];
            if (RELU) v = fmaxf(v, 0.0f);
            C[(long)gr * Ncols + gc] = v;
        }
    }
}

// ---------------------------------------------------------------------------
// agg init with self-loop term: agg[n,j] = dinv[n]^2 * xw[n,j]
//   xw lives in t buffer columns [0,D) with row stride LD
// ---------------------------------------------------------------------------
template<int D, int LD>
__global__ void k_agg_init(const float* __restrict__ t, float* __restrict__ agg) {
    long i = (long)blockIdx.x * blockDim.x + threadIdx.x;
    if (i >= (long)N_NODES * D) return;
    int n = (int)(i / D);
    int j = (int)(i % D);
    float di = g_dinv[n];
    agg[i] = di * di * t[(long)n * LD + j];
}

// ---------------------------------------------------------------------------
// Edge scatter:  agg[col] += dinv[row]*dinv[col] * xw[row]
//   D/4 lanes per edge, vectorized float4 loads + red.global.add.v4.f32
// ---------------------------------------------------------------------------
template<int D, int LD>
__global__ void k_scatter(const int* __restrict__ row, const int* __restrict__ col,
                          const float* __restrict__ t, float* __restrict__ agg, int E) {
    constexpr int LPE = D / 4;
    long tid = (long)blockIdx.x * blockDim.x + threadIdx.x;
    long e = tid / LPE;
    int  l = (int)(tid % LPE);
    if (e >= E) return;
    int r = row[e], c = col[e];
    float w = g_dinv[r] * g_dinv[c];
    float4 v = ((const float4*)(t + (long)r * LD))[l];
    float* dst = agg + (long)c * D + l * 4;
    asm volatile("red.global.add.v4.f32 [%0], {%1,%2,%3,%4};"
                 :: "l"(dst), "f"(v.x * w), "f"(v.y * w), "f"(v.z * w), "f"(v.w * w)
                 : "memory");
}

// ---------------------------------------------------------------------------
// Layer-1 Euler update: h1 += eps * tanh(z1 + agg1 + b1)
// ---------------------------------------------------------------------------
__global__ void k_update1(const float* __restrict__ b1) {
    long i = (long)blockIdx.x * blockDim.x + threadIdx.x;
    if (i >= (long)N_NODES * HID) return;
    int n = (int)(i / HID);
    int j = (int)(i % HID);
    float z = g_t1[(long)n * (2 * HID) + HID + j] + g_agg1[i] + b1[j];
    g_h1[i] += EPS_F * tanhf(z);
}

// ---------------------------------------------------------------------------
// Layer-2 Euler update + log_softmax (warp per node, 32 classes)
// ---------------------------------------------------------------------------
__global__ void k_final(const float* __restrict__ b2, float* __restrict__ out) {
    int warp = (blockIdx.x * blockDim.x + threadIdx.x) >> 5;
    int lane = threadIdx.x & 31;
    if (warp >= N_NODES) return;
    long base = (long)warp * CLS;
    float z = g_t2[(long)warp * (2 * CLS) + CLS + lane] + g_agg2[base + lane] + b2[lane];
    float v = g_h2[base + lane] + EPS_F * tanhf(z);
    float m = v;
#pragma unroll
    for (int o = 16; o > 0; o >>= 1) m = fmaxf(m, __shfl_xor_sync(0xffffffffu, m, o));
    float ex = expf(v - m);
    float s = ex;
#pragma unroll
    for (int o = 16; o > 0; o >>= 1) s += __shfl_xor_sync(0xffffffffu, s, o);
    out[base + lane] = v - m - logf(s);
}

// ---------------------------------------------------------------------------
// Launch
// ---------------------------------------------------------------------------
extern "C" void kernel_launch(void* const* d_in, const int* in_sizes, int n_in,
                              void* d_out, int out_size) {
    const float* x      = (const float*)d_in[0];
    const float* lin1_w = (const float*)d_in[1];
    const float* lin1_b = (const float*)d_in[2];
    const float* lin2_w = (const float*)d_in[3];
    const float* lin2_b = (const float*)d_in[4];
    const float* W1     = (const float*)d_in[5];
    const float* phi1   = (const float*)d_in[6];
    const float* b1     = (const float*)d_in[7];
    const float* W2     = (const float*)d_in[8];
    const float* phi2   = (const float*)d_in[9];
    const float* b2     = (const float*)d_in[10];
    const int*   ei     = (const int*)d_in[11];
    int E = in_sizes[11] / 2;
    const int* erow = ei;
    const int* ecol = ei + E;
    float* out = (float*)d_out;

    float *p_h1, *p_t1, *p_agg1, *p_h2, *p_t2, *p_agg2, *p_comb1, *p_comb2;
    cudaGetSymbolAddress((void**)&p_h1,    g_h1);
    cudaGetSymbolAddress((void**)&p_t1,    g_t1);
    cudaGetSymbolAddress((void**)&p_agg1,  g_agg1);
    cudaGetSymbolAddress((void**)&p_h2,    g_h2);
    cudaGetSymbolAddress((void**)&p_t2,    g_t2);
    cudaGetSymbolAddress((void**)&p_agg2,  g_agg2);
    cudaGetSymbolAddress((void**)&p_comb1, g_comb1);
    cudaGetSymbolAddress((void**)&p_comb2, g_comb2);

    const int TPB = 256;
    int mblocks = (N_NODES + 63) / 64;  // 1563

    // ---- graph normalization ----
    k_deg_init<<<(N_NODES + TPB - 1) / TPB, TPB>>>();
    k_deg_accum<<<(E + TPB - 1) / TPB, TPB>>>(ecol, E);
    k_dinv<<<(N_NODES + TPB - 1) / TPB, TPB>>>();

    // ---- combined (phi | antisymmetric) weights ----
    k_comb<<<(HID * HID + TPB - 1) / TPB, TPB>>>(W1, phi1, p_comb1, HID);
    k_comb<<<(CLS * CLS + TPB - 1) / TPB, TPB>>>(W2, phi2, p_comb2, CLS);

    // ---- h1 = relu(x @ lin1_w^T + lin1_b)   [N,128] ----
    k_gemm<64, 64, 16, 4, 4, true, true>
        <<<dim3(HID / 64, mblocks), 256>>>(x, lin1_w, lin1_b, p_h1, N_NODES, HID, F_IN);

    // ---- t1 = h1 @ comb1^T   [N,256]  (xw1 | z1) ----
    k_gemm<64, 64, 16, 4, 4, false, false>
        <<<dim3(2 * HID / 64, mblocks), 256>>>(p_h1, p_comb1, nullptr, p_t1, N_NODES, 2 * HID, HID);

    // ---- layer-1 message passing ----
    long n1 = (long)N_NODES * HID;
    k_agg_init<HID, 2 * HID><<<(int)((n1 + TPB - 1) / TPB), TPB>>>(p_t1, p_agg1);
    long s1 = (long)E * (HID / 4);
    k_scatter<HID, 2 * HID><<<(int)((s1 + TPB - 1) / TPB), TPB>>>(erow, ecol, p_t1, p_agg1, E);
    k_update1<<<(int)((n1 + TPB - 1) / TPB), TPB>>>(b1);

    // ---- h2 = h1 @ lin2_w^T + lin2_b   [N,32] ----
    k_gemm<64, 32, 32, 4, 4, false, true>
        <<<dim3(1, mblocks), 128>>>(p_h1, lin2_w, lin2_b, p_h2, N_NODES, CLS, HID);

    // ---- t2 = h2 @ comb2^T   [N,64]  (xw2 | z2) ----
    k_gemm<64, 64, 32, 4, 4, false, false>
        <<<dim3(1, mblocks), 256>>>(p_h2, p_comb2, nullptr, p_t2, N_NODES, 2 * CLS, CLS);

    // ---- layer-2 message passing ----
    long n2 = (long)N_NODES * CLS;
    k_agg_init<CLS, 2 * CLS><<<(int)((n2 + TPB - 1) / TPB), TPB>>>(p_t2, p_agg2);
    long s2 = (long)E * (CLS / 4);
    k_scatter<CLS, 2 * CLS><<<(int)((s2 + TPB - 1) / TPB), TPB>>>(erow, ecol, p_t2, p_agg2, E);

    // ---- final update + log_softmax ----
    k_final<<<(N_NODES * 32 + TPB - 1) / TPB, TPB>>>(b2, out);
}

// round 2
// speedup vs baseline: 1.6174x; 1.6174x over previous
#include <cuda_runtime.h>
#include <math.h>

#define N_NODES 100000
#define F_IN    256
#define HID     128
#define CLS     32
#define EPS_F   0.1f
#define GAMMA_F 0.1f

// ---------------------------------------------------------------------------
// Scratch (device globals -- no allocation allowed)
// ---------------------------------------------------------------------------
__device__ __align__(16) float g_deg  [N_NODES];
__device__ __align__(16) float g_dinv [N_NODES];
__device__ __align__(16) float g_h1   [(size_t)N_NODES * HID];   // 51.2 MB
__device__ __align__(16) float g_xw1  [(size_t)N_NODES * HID];   // 51.2 MB (dinv-scaled)
__device__ __align__(16) float g_z1   [(size_t)N_NODES * HID];   // 51.2 MB
__device__ __align__(16) float g_agg1 [(size_t)N_NODES * HID];   // 51.2 MB
__device__ __align__(16) float g_h2   [(size_t)N_NODES * CLS];
__device__ __align__(16) float g_xw2  [(size_t)N_NODES * CLS];
__device__ __align__(16) float g_z2   [(size_t)N_NODES * CLS];
__device__ __align__(16) float g_agg2 [(size_t)N_NODES * CLS];
__device__ __align__(16) float g_comb1[2 * HID * HID];
__device__ __align__(16) float g_comb2[2 * CLS * CLS];

// ---------------------------------------------------------------------------
// Degree / normalization
// ---------------------------------------------------------------------------
__global__ void k_deg_init() {
    int i = blockIdx.x * blockDim.x + threadIdx.x;
    if (i < N_NODES) g_deg[i] = 1.0f;  // self loop
}
__global__ void k_deg_accum(const int* __restrict__ col, int E) {
    int e = blockIdx.x * blockDim.x + threadIdx.x;
    if (e < E) atomicAdd(&g_deg[col[e]], 1.0f);
}
__global__ void k_dinv() {
    int i = blockIdx.x * blockDim.x + threadIdx.x;
    if (i < N_NODES) g_dinv[i] = rsqrtf(g_deg[i]);
}

// ---------------------------------------------------------------------------
// Combined weight: rows [0,d) = phi_w ; rows [d,2d) = W - W^T - gamma*I
// ---------------------------------------------------------------------------
__global__ void k_comb(const float* __restrict__ W, const float* __restrict__ phi,
                       float* __restrict__ comb, int d) {
    int i = blockIdx.x * blockDim.x + threadIdx.x;
    if (i >= d * d) return;
    int r = i / d, c = i % d;
    comb[r * d + c] = phi[i];
    comb[(d + r) * d + c] = W[r * d + c] - W[c * d + r] - ((r == c) ? GAMMA_F : 0.0f);
}

// ---------------------------------------------------------------------------
// Register-tiled fp32 GEMM: C[M,Ncols] = A[M,K] @ B[Ncols,K]^T
//   MODE 0: C = v (+bias)(+relu)
//   MODE 1: split -- gc < D: C[gr*D+gc]  = dinv[gr]*v   (xws buffer)
//                    gc >= D: C2[gr*D+gc-D] = v          (z buffer)
// Requires: K % BK == 0, BK % 4 == 0, Ncols % BN == 0.
// ---------------------------------------------------------------------------
template<int BM, int BN, int BK, int TM, int TN, int MODE, bool RELU, bool HASB>
__global__ void k_gemm(const float* __restrict__ A, const float* __restrict__ B,
                       const float* __restrict__ bias,
                       float* __restrict__ C, float* __restrict__ C2,
                       int M, int Ncols, int K, int D) {
    constexpr int THREADS = (BM / TM) * (BN / TN);
    __shared__ float As[BK][BM];
    __shared__ float Bs[BK][BN];

    int tid  = threadIdx.x;
    int tcol = tid % (BN / TN);
    int trow = tid / (BN / TN);
    int row0 = blockIdx.y * BM;
    int col0 = blockIdx.x * BN;

    float acc[TM][TN];
#pragma unroll
    for (int i = 0; i < TM; i++)
#pragma unroll
        for (int j = 0; j < TN; j++) acc[i][j] = 0.0f;

    constexpr int A_LOADS = (BM * BK / 4) / THREADS;
    constexpr int B_LOADS = (BN * BK / 4) / THREADS;

    for (int k0 = 0; k0 < K; k0 += BK) {
#pragma unroll
        for (int u = 0; u < A_LOADS; u++) {
            int idx = tid + u * THREADS;
            int r   = idx / (BK / 4);
            int c4  = idx % (BK / 4);
            int gr  = row0 + r;
            float4 v = make_float4(0.f, 0.f, 0.f, 0.f);
            if (gr < M) v = *(const float4*)(A + (long)gr * K + k0 + c4 * 4);
            As[c4 * 4 + 0][r] = v.x;
            As[c4 * 4 + 1][r] = v.y;
            As[c4 * 4 + 2][r] = v.z;
            As[c4 * 4 + 3][r] = v.w;
        }
#pragma unroll
        for (int u = 0; u < B_LOADS; u++) {
            int idx = tid + u * THREADS;
            int r   = idx / (BK / 4);
            int c4  = idx % (BK / 4);
            float4 v = *(const float4*)(B + (long)(col0 + r) * K + k0 + c4 * 4);
            Bs[c4 * 4 + 0][r] = v.x;
            Bs[c4 * 4 + 1][r] = v.y;
            Bs[c4 * 4 + 2][r] = v.z;
            Bs[c4 * 4 + 3][r] = v.w;
        }
        __syncthreads();

#pragma unroll
        for (int k = 0; k < BK; k++) {
            float ra[TM], rb[TN];
#pragma unroll
            for (int i = 0; i < TM; i += 4)
                *(float4*)&ra[i] = *(const float4*)&As[k][trow * TM + i];
#pragma unroll
            for (int j = 0; j < TN; j += 4)
                *(float4*)&rb[j] = *(const float4*)&Bs[k][tcol * TN + j];
#pragma unroll
            for (int i = 0; i < TM; i++)
#pragma unroll
                for (int j = 0; j < TN; j++)
                    acc[i][j] = fmaf(ra[i], rb[j], acc[i][j]);
        }
        __syncthreads();
    }

#pragma unroll
    for (int i = 0; i < TM; i++) {
        int gr = row0 + trow * TM + i;
        if (gr >= M) continue;
        float di = (MODE == 1) ? g_dinv[gr] : 0.0f;
#pragma unroll
        for (int j = 0; j < TN; j++) {
            int gc = col0 + tcol * TN + j;
            float v = acc[i][j];
            if (MODE == 0) {
                if (HASB) v += bias[gc];
                if (RELU) v = fmaxf(v, 0.0f);
                C[(long)gr * Ncols + gc] = v;
            } else {
                if (gc < D) C[(long)gr * D + gc] = di * v;
                else        C2[(long)gr * D + (gc - D)] = v;
            }
        }
    }
}

// ---------------------------------------------------------------------------
// agg init with self-loop: agg[n,:] = dinv[n] * xws[n,:]  (xws = dinv[n]*xw)
// ---------------------------------------------------------------------------
template<int D>
__global__ void k_agg_init(const float* __restrict__ xws, float* __restrict__ agg) {
    long i4 = (long)blockIdx.x * blockDim.x + threadIdx.x;
    if (i4 >= (long)N_NODES * D / 4) return;
    int n = (int)(i4 / (D / 4));
    float di = g_dinv[n];
    float4 v = ((const float4*)xws)[i4];
    v.x *= di; v.y *= di; v.z *= di; v.w *= di;
    ((float4*)agg)[i4] = v;
}

// ---------------------------------------------------------------------------
// Edge scatter:  agg[col] += dinv[col] * xws[row]   (xws pre-scaled by dinv[row])
// ---------------------------------------------------------------------------
template<int D>
__global__ void k_scatter(const int* __restrict__ row, const int* __restrict__ col,
                          const float* __restrict__ xws, float* __restrict__ agg, int E) {
    constexpr int LPE = D / 4;
    long tid = (long)blockIdx.x * blockDim.x + threadIdx.x;
    long e = tid / LPE;
    int  l = (int)(tid % LPE);
    if (e >= E) return;
    int r = row[e], c = col[e];
    float w = g_dinv[c];
    float4 v = ((const float4*)(xws + (long)r * D))[l];
    float* dst = agg + (long)c * D + l * 4;
    asm volatile("red.global.add.v4.f32 [%0], {%1,%2,%3,%4};"
                 :: "l"(dst), "f"(v.x * w), "f"(v.y * w), "f"(v.z * w), "f"(v.w * w)
                 : "memory");
}

// ---------------------------------------------------------------------------
// Layer-1 Euler update (vectorized): h1 += eps * tanh(z1 + agg1 + b1)
// ---------------------------------------------------------------------------
__global__ void k_update1(const float* __restrict__ b1) {
    long i4 = (long)blockIdx.x * blockDim.x + threadIdx.x;
    if (i4 >= (long)N_NODES * HID / 4) return;
    int j4 = (int)(i4 % (HID / 4));
    float4 z = ((const float4*)g_z1)[i4];
    float4 a = ((const float4*)g_agg1)[i4];
    float4 b = ((const float4*)b1)[j4];
    float4 h = ((const float4*)g_h1)[i4];
    h.x += EPS_F * tanhf(z.x + a.x + b.x);
    h.y += EPS_F * tanhf(z.y + a.y + b.y);
    h.z += EPS_F * tanhf(z.z + a.z + b.z);
    h.w += EPS_F * tanhf(z.w + a.w + b.w);
    ((float4*)g_h1)[i4] = h;
}

// ---------------------------------------------------------------------------
// Layer-2 Euler update + log_softmax (warp per node)
// ---------------------------------------------------------------------------
__global__ void k_final(const float* __restrict__ b2, float* __restrict__ out) {
    int warp = (blockIdx.x * blockDim.x + threadIdx.x) >> 5;
    int lane = threadIdx.x & 31;
    if (warp >= N_NODES) return;
    long base = (long)warp * CLS;
    float z = g_z2[base + lane] + g_agg2[base + lane] + b2[lane];
    float v = g_h2[base + lane] + EPS_F * tanhf(z);
    float m = v;
#pragma unroll
    for (int o = 16; o > 0; o >>= 1) m = fmaxf(m, __shfl_xor_sync(0xffffffffu, m, o));
    float ex = expf(v - m);
    float s = ex;
#pragma unroll
    for (int o = 16; o > 0; o >>= 1) s += __shfl_xor_sync(0xffffffffu, s, o);
    out[base + lane] = v - m - logf(s);
}

// ---------------------------------------------------------------------------
// Launch
// ---------------------------------------------------------------------------
extern "C" void kernel_launch(void* const* d_in, const int* in_sizes, int n_in,
                              void* d_out, int out_size) {
    const float* x      = (const float*)d_in[0];
    const float* lin1_w = (const float*)d_in[1];
    const float* lin1_b = (const float*)d_in[2];
    const float* lin2_w = (const float*)d_in[3];
    const float* lin2_b = (const float*)d_in[4];
    const float* W1     = (const float*)d_in[5];
    const float* phi1   = (const float*)d_in[6];
    const float* b1     = (const float*)d_in[7];
    const float* W2     = (const float*)d_in[8];
    const float* phi2   = (const float*)d_in[9];
    const float* b2     = (const float*)d_in[10];
    const int*   ei     = (const int*)d_in[11];
    int E = in_sizes[11] / 2;
    const int* erow = ei;
    const int* ecol = ei + E;
    float* out = (float*)d_out;

    float *p_h1, *p_xw1, *p_z1, *p_agg1, *p_h2, *p_xw2, *p_z2, *p_agg2, *p_c1, *p_c2;
    cudaGetSymbolAddress((void**)&p_h1,   g_h1);
    cudaGetSymbolAddress((void**)&p_xw1,  g_xw1);
    cudaGetSymbolAddress((void**)&p_z1,   g_z1);
    cudaGetSymbolAddress((void**)&p_agg1, g_agg1);
    cudaGetSymbolAddress((void**)&p_h2,   g_h2);
    cudaGetSymbolAddress((void**)&p_xw2,  g_xw2);
    cudaGetSymbolAddress((void**)&p_z2,   g_z2);
    cudaGetSymbolAddress((void**)&p_agg2, g_agg2);
    cudaGetSymbolAddress((void**)&p_c1,   g_comb1);
    cudaGetSymbolAddress((void**)&p_c2,   g_comb2);

    const int TPB = 256;
    int mb128 = (N_NODES + 127) / 128;  // 782

    // ---- graph normalization ----
    k_deg_init <<<(N_NODES + TPB - 1) / TPB, TPB>>>();
    k_deg_accum<<<(E + TPB - 1) / TPB, TPB>>>(ecol, E);
    k_dinv     <<<(N_NODES + TPB - 1) / TPB, TPB>>>();

    // ---- combined weights ----
    k_comb<<<(HID * HID + TPB - 1) / TPB, TPB>>>(W1, phi1, p_c1, HID);
    k_comb<<<(CLS * CLS + TPB - 1) / TPB, TPB>>>(W2, phi2, p_c2, CLS);

    // ---- h1 = relu(x @ lin1_w^T + lin1_b)   [N,128] ----
    k_gemm<128, 64, 16, 8, 4, 0, true, true>
        <<<dim3(HID / 64, mb128), 256>>>(x, lin1_w, lin1_b, p_h1, nullptr, N_NODES, HID, F_IN, 0);

    // ---- (xw1|z1) = h1 @ comb1^T   [N,256], split epilogue ----
    k_gemm<128, 64, 16, 8, 4, 1, false, false>
        <<<dim3(2 * HID / 64, mb128), 256>>>(p_h1, p_c1, nullptr, p_xw1, p_z1, N_NODES, 2 * HID, HID, HID);

    // ---- layer-1 message passing ----
    long n1_4 = (long)N_NODES * HID / 4;
    k_agg_init<HID><<<(int)((n1_4 + TPB - 1) / TPB), TPB>>>(p_xw1, p_agg1);
    long s1 = (long)E * (HID / 4);
    k_scatter<HID><<<(int)((s1 + TPB - 1) / TPB), TPB>>>(erow, ecol, p_xw1, p_agg1, E);
    k_update1<<<(int)((n1_4 + TPB - 1) / TPB), TPB>>>(b1);

    // ---- h2 = h1 @ lin2_w^T + lin2_b   [N,32] ----
    k_gemm<128, 32, 16, 8, 4, 0, false, true>
        <<<dim3(1, mb128), 128>>>(p_h1, lin2_w, lin2_b, p_h2, nullptr, N_NODES, CLS, HID, 0);

    // ---- (xw2|z2) = h2 @ comb2^T   [N,64], split epilogue ----
    k_gemm<128, 64, 16, 8, 4, 1, false, false>
        <<<dim3(1, mb128), 256>>>(p_h2, p_c2, nullptr, p_xw2, p_z2, N_NODES, 2 * CLS, CLS, CLS);

    // ---- layer-2 message passing ----
    long n2_4 = (long)N_NODES * CLS / 4;
    k_agg_init<CLS><<<(int)((n2_4 + TPB - 1) / TPB), TPB>>>(p_xw2, p_agg2);
    long s2 = (long)E * (CLS / 4);
    k_scatter<CLS><<<(int)((s2 + TPB - 1) / TPB), TPB>>>(erow, ecol, p_xw2, p_agg2, E);

    // ---- final update + log_softmax ----
    k_final<<<(N_NODES * 32 + TPB - 1) / TPB, TPB>>>(b2, out);
}

// round 3
// speedup vs baseline: 2.3697x; 1.4651x over previous
#include <cuda_runtime.h>
#include <math.h>
#include <stdint.h>

#define N_NODES 100000
#define F_IN    256
#define HID     128
#define CLS     32
#define EPS_F   0.1f
#define GAMMA_F 0.1f

// ---------------------------------------------------------------------------
// Scratch (device globals -- no allocation allowed)
// ---------------------------------------------------------------------------
__device__ __align__(16) float g_deg  [N_NODES];
__device__ __align__(16) float g_dinv [N_NODES];
__device__ __align__(16) float g_h1   [(size_t)N_NODES * HID];
__device__ __align__(16) float g_xw1  [(size_t)N_NODES * HID];
__device__ __align__(16) float g_z1   [(size_t)N_NODES * HID];
__device__ __align__(16) float g_agg1 [(size_t)N_NODES * HID];
__device__ __align__(16) float g_h2   [(size_t)N_NODES * CLS];
__device__ __align__(16) float g_xw2  [(size_t)N_NODES * CLS];
__device__ __align__(16) float g_z2   [(size_t)N_NODES * CLS];
__device__ __align__(16) float g_agg2 [(size_t)N_NODES * CLS];
__device__ __align__(16) float g_comb1[2 * HID * HID];
__device__ __align__(16) float g_comb2[2 * CLS * CLS];

// ---------------------------------------------------------------------------
// Degree / normalization
// ---------------------------------------------------------------------------
__global__ void k_deg_init() {
    int i = blockIdx.x * blockDim.x + threadIdx.x;
    if (i < N_NODES) g_deg[i] = 1.0f;
}
__global__ void k_deg_accum(const int* __restrict__ col, int E) {
    int e = blockIdx.x * blockDim.x + threadIdx.x;
    if (e < E) atomicAdd(&g_deg[col[e]], 1.0f);
}
__global__ void k_dinv() {
    int i = blockIdx.x * blockDim.x + threadIdx.x;
    if (i < N_NODES) g_dinv[i] = rsqrtf(g_deg[i]);
}

// ---------------------------------------------------------------------------
// Combined weight: rows [0,d) = phi_w ; rows [d,2d) = W - W^T - gamma*I
// ---------------------------------------------------------------------------
__global__ void k_comb(const float* __restrict__ W, const float* __restrict__ phi,
                       float* __restrict__ comb, int d) {
    int i = blockIdx.x * blockDim.x + threadIdx.x;
    if (i >= d * d) return;
    int r = i / d, c = i % d;
    comb[r * d + c] = phi[i];
    comb[(d + r) * d + c] = W[r * d + c] - W[c * d + r] - ((r == c) ? GAMMA_F : 0.0f);
}

// ---------------------------------------------------------------------------
// TF32 helpers
// ---------------------------------------------------------------------------
__device__ __forceinline__ uint32_t f2tf(float x) {
    uint32_t r;
    asm("cvt.rna.tf32.f32 %0, %1;" : "=r"(r) : "f"(x));
    return r;
}
__device__ __forceinline__ void mma_tf32(float c[4], const uint32_t a[4], const uint32_t b[2]) {
    asm("mma.sync.aligned.m16n8k8.row.col.f32.tf32.tf32.f32 "
        "{%0,%1,%2,%3}, {%4,%5,%6,%7}, {%8,%9}, {%0,%1,%2,%3};"
        : "+f"(c[0]), "+f"(c[1]), "+f"(c[2]), "+f"(c[3])
        : "r"(a[0]), "r"(a[1]), "r"(a[2]), "r"(a[3]), "r"(b[0]), "r"(b[1]));
}

// ---------------------------------------------------------------------------
// TF32 MMA GEMM:  C[M,Ncols] = A[M,K] @ B[Ncols,K]^T
//   Block 128 x BN, BK=32, 8 warps (4 in M x 2 in N), warp tile 32 x WN.
//   MODE 0: C = v (+bias)(+relu)
//   MODE 1: gc <  D: C (xws) = dinv[gr]*v ; C3 (agg) = dinv[gr]^2*v
//           gc >= D: C2 (z)  = v
//   Requires K % 32 == 0, Ncols % BN == 0.
// ---------------------------------------------------------------------------
template<int BN, int WN, int MODE, bool RELU, bool HASB>
__global__ void k_mma(const float* __restrict__ A, const float* __restrict__ B,
                      const float* __restrict__ bias,
                      float* __restrict__ C, float* __restrict__ C2, float* __restrict__ C3,
                      int M, int Ncols, int K, int D) {
    constexpr int BM = 128, BK = 32, BKP = BK + 4;
    constexpr int MT = 2, NT = WN / 8;
    __shared__ uint32_t As[BM][BKP];
    __shared__ uint32_t Bs[BN][BKP];

    const int tid  = threadIdx.x;
    const int warp = tid >> 5, lane = tid & 31;
    const int grp  = lane >> 2, qid = lane & 3;
    const int wm0  = (warp & 3) * 32;
    const int wn0  = (warp >> 2) * WN;
    const int row0 = blockIdx.y * BM;
    const int col0 = blockIdx.x * BN;

    float acc[MT][NT][4];
#pragma unroll
    for (int i = 0; i < MT; i++)
#pragma unroll
        for (int j = 0; j < NT; j++)
#pragma unroll
            for (int q = 0; q < 4; q++) acc[i][j][q] = 0.0f;

    constexpr int AL = (BM * BK / 4) / 256;   // 4
    constexpr int BL = (BN * BK / 4) / 256;   // 2 (BN=64) or 1 (BN=32)

    for (int k0 = 0; k0 < K; k0 += BK) {
#pragma unroll
        for (int u = 0; u < AL; u++) {
            int idx = tid + u * 256;
            int r = idx >> 3, c4 = idx & 7;
            int gr = row0 + r;
            float4 v = make_float4(0.f, 0.f, 0.f, 0.f);
            if (gr < M) v = *(const float4*)(A + (size_t)gr * K + k0 + c4 * 4);
            uint32_t* p = &As[r][c4 * 4];
            p[0] = f2tf(v.x); p[1] = f2tf(v.y); p[2] = f2tf(v.z); p[3] = f2tf(v.w);
        }
#pragma unroll
        for (int u = 0; u < BL; u++) {
            int idx = tid + u * 256;
            int r = idx >> 3, c4 = idx & 7;
            float4 v = *(const float4*)(B + (size_t)(col0 + r) * K + k0 + c4 * 4);
            uint32_t* p = &Bs[r][c4 * 4];
            p[0] = f2tf(v.x); p[1] = f2tf(v.y); p[2] = f2tf(v.z); p[3] = f2tf(v.w);
        }
        __syncthreads();

#pragma unroll
        for (int kk = 0; kk < BK / 8; kk++) {
            const int kb = kk * 8;
            uint32_t af[MT][4], bf[NT][2];
#pragma unroll
            for (int i = 0; i < MT; i++) {
                int m = wm0 + i * 16 + grp;
                af[i][0] = As[m    ][kb + qid];
                af[i][1] = As[m + 8][kb + qid];
                af[i][2] = As[m    ][kb + qid + 4];
                af[i][3] = As[m + 8][kb + qid + 4];
            }
#pragma unroll
            for (int j = 0; j < NT; j++) {
                int n = wn0 + j * 8 + grp;
                bf[j][0] = Bs[n][kb + qid];
                bf[j][1] = Bs[n][kb + qid + 4];
            }
#pragma unroll
            for (int i = 0; i < MT; i++)
#pragma unroll
                for (int j = 0; j < NT; j++)
                    mma_tf32(acc[i][j], af[i], bf[j]);
        }
        __syncthreads();
    }

    // ---- epilogue ----
#pragma unroll
    for (int i = 0; i < MT; i++) {
#pragma unroll
        for (int h = 0; h < 2; h++) {
            int gr = row0 + wm0 + i * 16 + grp + h * 8;
            if (gr >= M) continue;
            float di = (MODE == 1) ? g_dinv[gr] : 0.0f;
#pragma unroll
            for (int j = 0; j < NT; j++) {
                int gc = col0 + wn0 + j * 8 + 2 * qid;
                float v0 = acc[i][j][2 * h];
                float v1 = acc[i][j][2 * h + 1];
                if (MODE == 0) {
                    if (HASB) { v0 += bias[gc]; v1 += bias[gc + 1]; }
                    if (RELU) { v0 = fmaxf(v0, 0.f); v1 = fmaxf(v1, 0.f); }
                    *(float2*)(C + (size_t)gr * Ncols + gc) = make_float2(v0, v1);
                } else {
                    if (gc < D) {
                        *(float2*)(C  + (size_t)gr * D + gc) = make_float2(di * v0, di * v1);
                        *(float2*)(C3 + (size_t)gr * D + gc) = make_float2(di * di * v0, di * di * v1);
                    } else {
                        *(float2*)(C2 + (size_t)gr * D + gc - D) = make_float2(v0, v1);
                    }
                }
            }
        }
    }
}

// ---------------------------------------------------------------------------
// Edge scatter:  agg[col] += dinv[col] * xws[row]
// ---------------------------------------------------------------------------
template<int D>
__global__ void k_scatter(const int* __restrict__ row, const int* __restrict__ col,
                          const float* __restrict__ xws, float* __restrict__ agg, int E) {
    constexpr int LPE = D / 4;
    long tid = (long)blockIdx.x * blockDim.x + threadIdx.x;
    long e = tid / LPE;
    int  l = (int)(tid % LPE);
    if (e >= E) return;
    int r = row[e], c = col[e];
    float w = g_dinv[c];
    float4 v = ((const float4*)(xws + (long)r * D))[l];
    float* dst = agg + (long)c * D + l * 4;
    asm volatile("red.global.add.v4.f32 [%0], {%1,%2,%3,%4};"
                 :: "l"(dst), "f"(v.x * w), "f"(v.y * w), "f"(v.z * w), "f"(v.w * w)
                 : "memory");
}

// ---------------------------------------------------------------------------
// Layer-1 Euler update: h1 += eps * tanh(z1 + agg1 + b1)
// ---------------------------------------------------------------------------
__global__ void k_update1(const float* __restrict__ b1) {
    long i4 = (long)blockIdx.x * blockDim.x + threadIdx.x;
    if (i4 >= (long)N_NODES * HID / 4) return;
    int j4 = (int)(i4 % (HID / 4));
    float4 z = ((const float4*)g_z1)[i4];
    float4 a = ((const float4*)g_agg1)[i4];
    float4 b = ((const float4*)b1)[j4];
    float4 h = ((const float4*)g_h1)[i4];
    h.x += EPS_F * tanhf(z.x + a.x + b.x);
    h.y += EPS_F * tanhf(z.y + a.y + b.y);
    h.z += EPS_F * tanhf(z.z + a.z + b.z);
    h.w += EPS_F * tanhf(z.w + a.w + b.w);
    ((float4*)g_h1)[i4] = h;
}

// ---------------------------------------------------------------------------
// Layer-2 Euler update + log_softmax (warp per node)
// ---------------------------------------------------------------------------
__global__ void k_final(const float* __restrict__ b2, float* __restrict__ out) {
    int warp = (blockIdx.x * blockDim.x + threadIdx.x) >> 5;
    int lane = threadIdx.x & 31;
    if (warp >= N_NODES) return;
    long base = (long)warp * CLS;
    float z = g_z2[base + lane] + g_agg2[base + lane] + b2[lane];
    float v = g_h2[base + lane] + EPS_F * tanhf(z);
    float m = v;
#pragma unroll
    for (int o = 16; o > 0; o >>= 1) m = fmaxf(m, __shfl_xor_sync(0xffffffffu, m, o));
    float ex = expf(v - m);
    float s = ex;
#pragma unroll
    for (int o = 16; o > 0; o >>= 1) s += __shfl_xor_sync(0xffffffffu, s, o);
    out[base + lane] = v - m - logf(s);
}

// ---------------------------------------------------------------------------
// Launch
// ---------------------------------------------------------------------------
extern "C" void kernel_launch(void* const* d_in, const int* in_sizes, int n_in,
                              void* d_out, int out_size) {
    const float* x      = (const float*)d_in[0];
    const float* lin1_w = (const float*)d_in[1];
    const float* lin1_b = (const float*)d_in[2];
    const float* lin2_w = (const float*)d_in[3];
    const float* lin2_b = (const float*)d_in[4];
    const float* W1     = (const float*)d_in[5];
    const float* phi1   = (const float*)d_in[6];
    const float* b1     = (const float*)d_in[7];
    const float* W2     = (const float*)d_in[8];
    const float* phi2   = (const float*)d_in[9];
    const float* b2     = (const float*)d_in[10];
    const int*   ei     = (const int*)d_in[11];
    int E = in_sizes[11] / 2;
    const int* erow = ei;
    const int* ecol = ei + E;
    float* out = (float*)d_out;

    float *p_h1, *p_xw1, *p_z1, *p_agg1, *p_h2, *p_xw2, *p_z2, *p_agg2, *p_c1, *p_c2;
    cudaGetSymbolAddress((void**)&p_h1,   g_h1);
    cudaGetSymbolAddress((void**)&p_xw1,  g_xw1);
    cudaGetSymbolAddress((void**)&p_z1,   g_z1);
    cudaGetSymbolAddress((void**)&p_agg1, g_agg1);
    cudaGetSymbolAddress((void**)&p_h2,   g_h2);
    cudaGetSymbolAddress((void**)&p_xw2,  g_xw2);
    cudaGetSymbolAddress((void**)&p_z2,   g_z2);
    cudaGetSymbolAddress((void**)&p_agg2, g_agg2);
    cudaGetSymbolAddress((void**)&p_c1,   g_comb1);
    cudaGetSymbolAddress((void**)&p_c2,   g_comb2);

    const int TPB = 256;
    int mb128 = (N_NODES + 127) / 128;  // 782

    // ---- graph normalization ----
    k_deg_init <<<(N_NODES + TPB - 1) / TPB, TPB>>>();
    k_deg_accum<<<(E + TPB - 1) / TPB, TPB>>>(ecol, E);
    k_dinv     <<<(N_NODES + TPB - 1) / TPB, TPB>>>();

    // ---- combined weights ----
    k_comb<<<(HID * HID + TPB - 1) / TPB, TPB>>>(W1, phi1, p_c1, HID);
    k_comb<<<(CLS * CLS + TPB - 1) / TPB, TPB>>>(W2, phi2, p_c2, CLS);

    // ---- h1 = relu(x @ lin1_w^T + lin1_b)   [N,128] ----
    k_mma<64, 32, 0, true, true>
        <<<dim3(2, mb128), 256>>>(x, lin1_w, lin1_b, p_h1, nullptr, nullptr, N_NODES, HID, F_IN, 0);

    // ---- (xw1|z1|agg1) = h1 @ comb1^T   [N,256] split+agg epilogue ----
    k_mma<64, 32, 1, false, false>
        <<<dim3(4, mb128), 256>>>(p_h1, p_c1, nullptr, p_xw1, p_z1, p_agg1, N_NODES, 2 * HID, HID, HID);

    // ---- layer-1 scatter + update ----
    long s1 = (long)E * (HID / 4);
    k_scatter<HID><<<(int)((s1 + TPB - 1) / TPB), TPB>>>(erow, ecol, p_xw1, p_agg1, E);
    long n1_4 = (long)N_NODES * HID / 4;
    k_update1<<<(int)((n1_4 + TPB - 1) / TPB), TPB>>>(b1);

    // ---- h2 = h1 @ lin2_w^T + lin2_b   [N,32] ----
    k_mma<32, 16, 0, false, true>
        <<<dim3(1, mb128), 256>>>(p_h1, lin2_w, lin2_b, p_h2, nullptr, nullptr, N_NODES, CLS, HID, 0);

    // ---- (xw2|z2|agg2) = h2 @ comb2^T   [N,64] split+agg epilogue ----
    k_mma<64, 32, 1, false, false>
        <<<dim3(1, mb128), 256>>>(p_h2, p_c2, nullptr, p_xw2, p_z2, p_agg2, N_NODES, 2 * CLS, CLS, CLS);

    // ---- layer-2 scatter ----
    long s2 = (long)E * (CLS / 4);
    k_scatter<CLS><<<(int)((s2 + TPB - 1) / TPB), TPB>>>(erow, ecol, p_xw2, p_agg2, E);

    // ---- final update + log_softmax ----
    k_final<<<(N_NODES * 32 + TPB - 1) / TPB, TPB>>>(b2, out);
}

// round 4
// speedup vs baseline: 3.6172x; 1.5265x over previous
#include <cuda_runtime.h>
#include <cuda_bf16.h>
#include <math.h>
#include <stdint.h>

#define N_NODES 100000
#define F_IN    256
#define HID     128
#define CLS     32
#define E_MAX   1600000
#define EPS_F   0.1f
#define GAMMA_F 0.1f

// ---------------------------------------------------------------------------
// Scratch (device globals -- no allocation allowed)
// ---------------------------------------------------------------------------
__device__ __align__(16) int      g_degi [N_NODES];
__device__ __align__(16) int      g_scan [N_NODES];
__device__ __align__(16) int      g_bsum [128];
__device__ __align__(16) int      g_off  [N_NODES + 1];
__device__ __align__(16) int      g_cur  [N_NODES];
__device__ __align__(16) int      g_csr  [E_MAX];
__device__ __align__(16) float    g_dinv [N_NODES];
__device__ __align__(16) float    g_h1   [(size_t)N_NODES * HID];      // 51.2 MB
__device__ __align__(16) uint32_t g_xw1b [(size_t)N_NODES * HID / 2];  // 25.6 MB bf16x2
__device__ __align__(16) float    g_z1   [(size_t)N_NODES * HID];      // 51.2 MB
__device__ __align__(16) float    g_h2   [(size_t)N_NODES * CLS];
__device__ __align__(16) float    g_xw2  [(size_t)N_NODES * CLS];
__device__ __align__(16) float    g_z2   [(size_t)N_NODES * CLS];
__device__ __align__(16) float    g_comb1[2 * HID * HID];
__device__ __align__(16) float    g_comb2[2 * CLS * CLS];

// ---------------------------------------------------------------------------
// Degree / CSR build
// ---------------------------------------------------------------------------
__global__ void k_deg0() {
    int i = blockIdx.x * blockDim.x + threadIdx.x;
    if (i < N_NODES) g_degi[i] = 0;
}
__global__ void k_deg_accum(const int* __restrict__ col, int E) {
    int e = blockIdx.x * blockDim.x + threadIdx.x;
    if (e < E) atomicAdd(&g_degi[col[e]], 1);
}
// Block-wise inclusive scan (1024/block)
__global__ void k_scan1(int n) {
    __shared__ int sh[1024];
    int i = blockIdx.x * 1024 + threadIdx.x;
    int v = (i < n) ? g_degi[i] : 0;
    sh[threadIdx.x] = v;
    __syncthreads();
    for (int o = 1; o < 1024; o <<= 1) {
        int t = (threadIdx.x >= o) ? sh[threadIdx.x - o] : 0;
        __syncthreads();
        sh[threadIdx.x] += t;
        __syncthreads();
    }
    if (i < n) g_scan[i] = sh[threadIdx.x];
    if (threadIdx.x == 1023) g_bsum[blockIdx.x] = sh[1023];
}
__global__ void k_scan2(int nb) {
    __shared__ int sh[128];
    int v = (threadIdx.x < nb) ? g_bsum[threadIdx.x] : 0;
    sh[threadIdx.x] = v;
    __syncthreads();
    for (int o = 1; o < 128; o <<= 1) {
        int t = (threadIdx.x >= o) ? sh[threadIdx.x - o] : 0;
        __syncthreads();
        sh[threadIdx.x] += t;
        __syncthreads();
    }
    if (threadIdx.x < nb) g_bsum[threadIdx.x] = sh[threadIdx.x];
}
__global__ void k_scan3(int n) {
    int i = blockIdx.x * 1024 + threadIdx.x;
    if (i >= n) return;
    int add = (blockIdx.x > 0) ? g_bsum[blockIdx.x - 1] : 0;
    int inc = g_scan[i] + add;
    int off = inc - g_degi[i];
    g_off[i] = off;
    g_cur[i] = off;
    if (i == n - 1) g_off[n] = inc;
}
__global__ void k_dinv() {
    int i = blockIdx.x * blockDim.x + threadIdx.x;
    if (i < N_NODES) g_dinv[i] = rsqrtf((float)g_degi[i] + 1.0f);
}
__global__ void k_place(const int* __restrict__ row, const int* __restrict__ col, int E) {
    int e = blockIdx.x * blockDim.x + threadIdx.x;
    if (e >= E) return;
    int c = col[e];
    int p = atomicAdd(&g_cur[c], 1);
    g_csr[p] = row[e];
}

// ---------------------------------------------------------------------------
// Combined weight: rows [0,d) = phi_w ; rows [d,2d) = W - W^T - gamma*I
// ---------------------------------------------------------------------------
__global__ void k_comb(const float* __restrict__ W, const float* __restrict__ phi,
                       float* __restrict__ comb, int d) {
    int i = blockIdx.x * blockDim.x + threadIdx.x;
    if (i >= d * d) return;
    int r = i / d, c = i % d;
    comb[r * d + c] = phi[i];
    comb[(d + r) * d + c] = W[r * d + c] - W[c * d + r] - ((r == c) ? GAMMA_F : 0.0f);
}

// ---------------------------------------------------------------------------
// TF32 helpers
// ---------------------------------------------------------------------------
__device__ __forceinline__ uint32_t f2tf(float x) {
    uint32_t r;
    asm("cvt.rna.tf32.f32 %0, %1;" : "=r"(r) : "f"(x));
    return r;
}
__device__ __forceinline__ void mma_tf32(float c[4], const uint32_t a[4], const uint32_t b[2]) {
    asm("mma.sync.aligned.m16n8k8.row.col.f32.tf32.tf32.f32 "
        "{%0,%1,%2,%3}, {%4,%5,%6,%7}, {%8,%9}, {%0,%1,%2,%3};"
        : "+f"(c[0]), "+f"(c[1]), "+f"(c[2]), "+f"(c[3])
        : "r"(a[0]), "r"(a[1]), "r"(a[2]), "r"(a[3]), "r"(b[0]), "r"(b[1]));
}

// ---------------------------------------------------------------------------
// TF32 MMA GEMM:  C[M,Ncols] = A[M,K] @ B[Ncols,K]^T
//   MODE 0: C = v (+bias)(+relu)                          -> C (f32)
//   MODE 1: gc<D: xws bf16x2 = dinv*v -> Cb ; else z -> C2
//   MODE 2: gc<D: xws f32    = dinv*v -> C  ; else z -> C2
// ---------------------------------------------------------------------------
template<int BN, int WN, int MODE, bool RELU, bool HASB>
__global__ void k_mma(const float* __restrict__ A, const float* __restrict__ B,
                      const float* __restrict__ bias,
                      float* __restrict__ C, float* __restrict__ C2,
                      uint32_t* __restrict__ Cb,
                      int M, int Ncols, int K, int D) {
    constexpr int BM = 128, BK = 32, BKP = BK + 4;
    constexpr int MT = 2, NT = WN / 8;
    __shared__ uint32_t As[BM][BKP];
    __shared__ uint32_t Bs[BN][BKP];

    const int tid  = threadIdx.x;
    const int warp = tid >> 5, lane = tid & 31;
    const int grp  = lane >> 2, qid = lane & 3;
    const int wm0  = (warp & 3) * 32;
    const int wn0  = (warp >> 2) * WN;
    const int row0 = blockIdx.y * BM;
    const int col0 = blockIdx.x * BN;

    float acc[MT][NT][4];
#pragma unroll
    for (int i = 0; i < MT; i++)
#pragma unroll
        for (int j = 0; j < NT; j++)
#pragma unroll
            for (int q = 0; q < 4; q++) acc[i][j][q] = 0.0f;

    constexpr int AL = (BM * BK / 4) / 256;
    constexpr int BL = (BN * BK / 4) / 256;

    for (int k0 = 0; k0 < K; k0 += BK) {
#pragma unroll
        for (int u = 0; u < AL; u++) {
            int idx = tid + u * 256;
            int r = idx >> 3, c4 = idx & 7;
            int gr = row0 + r;
            float4 v = make_float4(0.f, 0.f, 0.f, 0.f);
            if (gr < M) v = *(const float4*)(A + (size_t)gr * K + k0 + c4 * 4);
            uint32_t* p = &As[r][c4 * 4];
            p[0] = f2tf(v.x); p[1] = f2tf(v.y); p[2] = f2tf(v.z); p[3] = f2tf(v.w);
        }
#pragma unroll
        for (int u = 0; u < BL; u++) {
            int idx = tid + u * 256;
            int r = idx >> 3, c4 = idx & 7;
            float4 v = *(const float4*)(B + (size_t)(col0 + r) * K + k0 + c4 * 4);
            uint32_t* p = &Bs[r][c4 * 4];
            p[0] = f2tf(v.x); p[1] = f2tf(v.y); p[2] = f2tf(v.z); p[3] = f2tf(v.w);
        }
        __syncthreads();

#pragma unroll
        for (int kk = 0; kk < BK / 8; kk++) {
            const int kb = kk * 8;
            uint32_t af[MT][4], bf[NT][2];
#pragma unroll
            for (int i = 0; i < MT; i++) {
                int m = wm0 + i * 16 + grp;
                af[i][0] = As[m    ][kb + qid];
                af[i][1] = As[m + 8][kb + qid];
                af[i][2] = As[m    ][kb + qid + 4];
                af[i][3] = As[m + 8][kb + qid + 4];
            }
#pragma unroll
            for (int j = 0; j < NT; j++) {
                int n = wn0 + j * 8 + grp;
                bf[j][0] = Bs[n][kb + qid];
                bf[j][1] = Bs[n][kb + qid + 4];
            }
#pragma unroll
            for (int i = 0; i < MT; i++)
#pragma unroll
                for (int j = 0; j < NT; j++)
                    mma_tf32(acc[i][j], af[i], bf[j]);
        }
        __syncthreads();
    }

#pragma unroll
    for (int i = 0; i < MT; i++) {
#pragma unroll
        for (int h = 0; h < 2; h++) {
            int gr = row0 + wm0 + i * 16 + grp + h * 8;
            if (gr >= M) continue;
            float di = (MODE != 0) ? g_dinv[gr] : 0.0f;
#pragma unroll
            for (int j = 0; j < NT; j++) {
                int gc = col0 + wn0 + j * 8 + 2 * qid;
                float v0 = acc[i][j][2 * h];
                float v1 = acc[i][j][2 * h + 1];
                if (MODE == 0) {
                    if (HASB) { v0 += bias[gc]; v1 += bias[gc + 1]; }
                    if (RELU) { v0 = fmaxf(v0, 0.f); v1 = fmaxf(v1, 0.f); }
                    *(float2*)(C + (size_t)gr * Ncols + gc) = make_float2(v0, v1);
                } else if (MODE == 1) {
                    if (gc < D) {
                        __nv_bfloat162 p = __float22bfloat162_rn(make_float2(di * v0, di * v1));
                        Cb[(size_t)gr * (D / 2) + gc / 2] = *reinterpret_cast<uint32_t*>(&p);
                    } else {
                        *(float2*)(C2 + (size_t)gr * D + gc - D) = make_float2(v0, v1);
                    }
                } else {
                    if (gc < D) *(float2*)(C  + (size_t)gr * D + gc) = make_float2(di * v0, di * v1);
                    else        *(float2*)(C2 + (size_t)gr * D + gc - D) = make_float2(v0, v1);
                }
            }
        }
    }
}

// ---------------------------------------------------------------------------
// Layer-1 CSR gather + fused Euler update (warp per node, lane = 4 cols)
//   h1[n] += eps * tanh(z1[n] + dinv[n]*(xws[n] + sum_in xws[r]) + b1)
// ---------------------------------------------------------------------------
__global__ void k_gather1(const float* __restrict__ b1) {
    int n    = (blockIdx.x * blockDim.x + threadIdx.x) >> 5;
    int lane = threadIdx.x & 31;
    if (n >= N_NODES) return;

    const uint2* xb = (const uint2*)g_xw1b;  // 4 bf16 per uint2
    int beg = g_off[n], end = g_off[n + 1];

    uint2 sv = xb[(size_t)n * 32 + lane];
    __nv_bfloat162 p0 = *reinterpret_cast<__nv_bfloat162*>(&sv.x);
    __nv_bfloat162 p1 = *reinterpret_cast<__nv_bfloat162*>(&sv.y);
    float2 f0 = __bfloat1622float2(p0);
    float2 f1 = __bfloat1622float2(p1);
    float sx = f0.x, sy = f0.y, sz = f1.x, sw = f1.y;

    for (int base = beg; base < end; base += 32) {
        int mye = base + lane;
        int r = (mye < end) ? g_csr[mye] : -1;
        int cnt = min(32, end - base);
        for (int j = 0; j < cnt; j++) {
            int rr = __shfl_sync(0xffffffffu, r, j);
            uint2 v = xb[(size_t)rr * 32 + lane];
            __nv_bfloat162 q0 = *reinterpret_cast<__nv_bfloat162*>(&v.x);
            __nv_bfloat162 q1 = *reinterpret_cast<__nv_bfloat162*>(&v.y);
            float2 g0 = __bfloat1622float2(q0);
            float2 g1 = __bfloat1622float2(q1);
            sx += g0.x; sy += g0.y; sz += g1.x; sw += g1.y;
        }
    }

    float u = g_dinv[n];
    size_t i4 = (size_t)n * 32 + lane;
    float4 z = ((const float4*)g_z1)[i4];
    float4 b = ((const float4*)b1)[lane];
    float4 h = ((const float4*)g_h1)[i4];
    h.x += EPS_F * tanhf(z.x + u * sx + b.x);
    h.y += EPS_F * tanhf(z.y + u * sy + b.y);
    h.z += EPS_F * tanhf(z.z + u * sz + b.z);
    h.w += EPS_F * tanhf(z.w + u * sw + b.w);
    ((float4*)g_h1)[i4] = h;
}

// ---------------------------------------------------------------------------
// Layer-2 CSR gather + fused update + log_softmax (warp per node, lane = col)
// ---------------------------------------------------------------------------
__global__ void k_gather2(const float* __restrict__ b2, float* __restrict__ out) {
    int n    = (blockIdx.x * blockDim.x + threadIdx.x) >> 5;
    int lane = threadIdx.x & 31;
    if (n >= N_NODES) return;

    int beg = g_off[n], end = g_off[n + 1];
    size_t base = (size_t)n * CLS;
    float s = g_xw2[base + lane];

    for (int eb = beg; eb < end; eb += 32) {
        int mye = eb + lane;
        int r = (mye < end) ? g_csr[mye] : -1;
        int cnt = min(32, end - eb);
        for (int j = 0; j < cnt; j++) {
            int rr = __shfl_sync(0xffffffffu, r, j);
            s += g_xw2[(size_t)rr * CLS + lane];
        }
    }

    float u = g_dinv[n];
    float z = g_z2[base + lane] + u * s + b2[lane];
    float v = g_h2[base + lane] + EPS_F * tanhf(z);
    float m = v;
#pragma unroll
    for (int o = 16; o > 0; o >>= 1) m = fmaxf(m, __shfl_xor_sync(0xffffffffu, m, o));
    float ex = expf(v - m);
    float sum = ex;
#pragma unroll
    for (int o = 16; o > 0; o >>= 1) sum += __shfl_xor_sync(0xffffffffu, sum, o);
    out[base + lane] = v - m - logf(sum);
}

// ---------------------------------------------------------------------------
// Launch
// ---------------------------------------------------------------------------
extern "C" void kernel_launch(void* const* d_in, const int* in_sizes, int n_in,
                              void* d_out, int out_size) {
    const float* x      = (const float*)d_in[0];
    const float* lin1_w = (const float*)d_in[1];
    const float* lin1_b = (const float*)d_in[2];
    const float* lin2_w = (const float*)d_in[3];
    const float* lin2_b = (const float*)d_in[4];
    const float* W1     = (const float*)d_in[5];
    const float* phi1   = (const float*)d_in[6];
    const float* b1     = (const float*)d_in[7];
    const float* W2     = (const float*)d_in[8];
    const float* phi2   = (const float*)d_in[9];
    const float* b2     = (const float*)d_in[10];
    const int*   ei     = (const int*)d_in[11];
    int E = in_sizes[11] / 2;
    const int* erow = ei;
    const int* ecol = ei + E;
    float* out = (float*)d_out;

    float *p_h1, *p_z1, *p_h2, *p_xw2, *p_z2, *p_c1, *p_c2;
    uint32_t* p_xw1b;
    cudaGetSymbolAddress((void**)&p_h1,   g_h1);
    cudaGetSymbolAddress((void**)&p_xw1b, g_xw1b);
    cudaGetSymbolAddress((void**)&p_z1,   g_z1);
    cudaGetSymbolAddress((void**)&p_h2,   g_h2);
    cudaGetSymbolAddress((void**)&p_xw2,  g_xw2);
    cudaGetSymbolAddress((void**)&p_z2,   g_z2);
    cudaGetSymbolAddress((void**)&p_c1,   g_comb1);
    cudaGetSymbolAddress((void**)&p_c2,   g_comb2);

    const int TPB = 256;
    int mb128 = (N_NODES + 127) / 128;          // 782
    int scan_blocks = (N_NODES + 1023) / 1024;  // 98
    int warp_blocks = (N_NODES * 32 + TPB - 1) / TPB;  // 12500

    // ---- CSR build + normalization ----
    k_deg0     <<<(N_NODES + TPB - 1) / TPB, TPB>>>();
    k_deg_accum<<<(E + TPB - 1) / TPB, TPB>>>(ecol, E);
    k_scan1    <<<scan_blocks, 1024>>>(N_NODES);
    k_scan2    <<<1, 128>>>(scan_blocks);
    k_scan3    <<<scan_blocks, 1024>>>(N_NODES);
    k_dinv     <<<(N_NODES + TPB - 1) / TPB, TPB>>>();
    k_place    <<<(E + TPB - 1) / TPB, TPB>>>(erow, ecol, E);

    // ---- combined weights ----
    k_comb<<<(HID * HID + TPB - 1) / TPB, TPB>>>(W1, phi1, p_c1, HID);
    k_comb<<<(CLS * CLS + TPB - 1) / TPB, TPB>>>(W2, phi2, p_c2, CLS);

    // ---- h1 = relu(x @ lin1_w^T + lin1_b)   [N,128] ----
    k_mma<64, 32, 0, true, true>
        <<<dim3(2, mb128), 256>>>(x, lin1_w, lin1_b, p_h1, nullptr, nullptr, N_NODES, HID, F_IN, 0);

    // ---- (xws1_bf16 | z1) = h1 @ comb1^T   [N,256] ----
    k_mma<64, 32, 1, false, false>
        <<<dim3(4, mb128), 256>>>(p_h1, p_c1, nullptr, nullptr, p_z1, p_xw1b, N_NODES, 2 * HID, HID, HID);

    // ---- layer-1 gather + fused Euler update ----
    k_gather1<<<warp_blocks, TPB>>>(b1);

    // ---- h2 = h1 @ lin2_w^T + lin2_b   [N,32] ----
    k_mma<32, 16, 0, false, true>
        <<<dim3(1, mb128), 256>>>(p_h1, lin2_w, lin2_b, p_h2, nullptr, nullptr, N_NODES, CLS, HID, 0);

    // ---- (xws2 | z2) = h2 @ comb2^T   [N,64] ----
    k_mma<64, 32, 2, false, false>
        <<<dim3(1, mb128), 256>>>(p_h2, p_c2, nullptr, p_xw2, p_z2, nullptr, N_NODES, 2 * CLS, CLS, CLS);

    // ---- layer-2 gather + fused update + log_softmax ----
    k_gather2<<<warp_blocks, TPB>>>(b2, out);
}

// round 5
// speedup vs baseline: 4.1659x; 1.1517x over previous
#include <cuda_runtime.h>
#include <cuda_bf16.h>
#include <math.h>
#include <stdint.h>

#define N_NODES 100000
#define F_IN    256
#define HID     128
#define CLS     32
#define E_MAX   1600000
#define EPS_F   0.1f
#define GAMMA_F 0.1f

// ---------------------------------------------------------------------------
// Scratch (device globals -- no allocation allowed)
// ---------------------------------------------------------------------------
__device__ __align__(16) int      g_degi [N_NODES];
__device__ __align__(16) int      g_scan [N_NODES];
__device__ __align__(16) int      g_bsum [128];
__device__ __align__(16) int      g_off  [N_NODES + 1];
__device__ __align__(16) int      g_cur  [N_NODES];
__device__ __align__(16) int      g_csr  [E_MAX];
__device__ __align__(16) float    g_dinv [N_NODES];
__device__ __align__(16) float    g_h1   [(size_t)N_NODES * HID];
__device__ __align__(16) uint32_t g_xw1b [(size_t)N_NODES * HID / 2];
__device__ __align__(16) float    g_z1   [(size_t)N_NODES * HID];
__device__ __align__(16) float    g_h2   [(size_t)N_NODES * CLS];
__device__ __align__(16) float    g_xw2  [(size_t)N_NODES * CLS];
__device__ __align__(16) float    g_z2   [(size_t)N_NODES * CLS];
__device__ __align__(16) float    g_comb1[2 * HID * HID];
__device__ __align__(16) float    g_comb2[2 * CLS * CLS];

// ---------------------------------------------------------------------------
// Degree / CSR build
// ---------------------------------------------------------------------------
__global__ void k_deg0() {
    int i = blockIdx.x * blockDim.x + threadIdx.x;
    if (i < N_NODES) g_degi[i] = 0;
}
__global__ void k_deg_accum(const int* __restrict__ col, int E) {
    int e = blockIdx.x * blockDim.x + threadIdx.x;
    if (e < E) atomicAdd(&g_degi[col[e]], 1);
}
__global__ void k_scan1(int n) {
    __shared__ int sh[1024];
    int i = blockIdx.x * 1024 + threadIdx.x;
    int v = (i < n) ? g_degi[i] : 0;
    sh[threadIdx.x] = v;
    __syncthreads();
    for (int o = 1; o < 1024; o <<= 1) {
        int t = (threadIdx.x >= o) ? sh[threadIdx.x - o] : 0;
        __syncthreads();
        sh[threadIdx.x] += t;
        __syncthreads();
    }
    if (i < n) g_scan[i] = sh[threadIdx.x];
    if (threadIdx.x == 1023) g_bsum[blockIdx.x] = sh[1023];
}
__global__ void k_scan2(int nb) {
    __shared__ int sh[128];
    int v = (threadIdx.x < nb) ? g_bsum[threadIdx.x] : 0;
    sh[threadIdx.x] = v;
    __syncthreads();
    for (int o = 1; o < 128; o <<= 1) {
        int t = (threadIdx.x >= o) ? sh[threadIdx.x - o] : 0;
        __syncthreads();
        sh[threadIdx.x] += t;
        __syncthreads();
    }
    if (threadIdx.x < nb) g_bsum[threadIdx.x] = sh[threadIdx.x];
}
// scan finalize + dinv fused
__global__ void k_scan3(int n) {
    int i = blockIdx.x * 1024 + threadIdx.x;
    if (i >= n) return;
    int d = g_degi[i];
    int add = (blockIdx.x > 0) ? g_bsum[blockIdx.x - 1] : 0;
    int inc = g_scan[i] + add;
    int off = inc - d;
    g_off[i] = off;
    g_cur[i] = off;
    g_dinv[i] = rsqrtf((float)d + 1.0f);
    if (i == n - 1) g_off[n] = inc;
}
__global__ void k_place(const int* __restrict__ row, const int* __restrict__ col, int E) {
    int e = blockIdx.x * blockDim.x + threadIdx.x;
    if (e >= E) return;
    int c = col[e];
    int p = atomicAdd(&g_cur[c], 1);
    g_csr[p] = row[e];
}

// ---------------------------------------------------------------------------
// Combined weights (both layers in one kernel)
// ---------------------------------------------------------------------------
__global__ void k_comb(const float* __restrict__ W1, const float* __restrict__ phi1,
                       const float* __restrict__ W2, const float* __restrict__ phi2) {
    int i = blockIdx.x * blockDim.x + threadIdx.x;
    if (i < HID * HID) {
        int r = i / HID, c = i % HID;
        g_comb1[r * HID + c] = phi1[i];
        g_comb1[(HID + r) * HID + c] = W1[r * HID + c] - W1[c * HID + r] - ((r == c) ? GAMMA_F : 0.0f);
    } else if (i < HID * HID + CLS * CLS) {
        int j = i - HID * HID;
        int r = j / CLS, c = j % CLS;
        g_comb2[r * CLS + c] = phi2[j];
        g_comb2[(CLS + r) * CLS + c] = W2[r * CLS + c] - W2[c * CLS + r] - ((r == c) ? GAMMA_F : 0.0f);
    }
}

// ---------------------------------------------------------------------------
// TF32 helpers
// ---------------------------------------------------------------------------
__device__ __forceinline__ uint32_t f2tf(float x) {
    uint32_t r;
    asm("cvt.rna.tf32.f32 %0, %1;" : "=r"(r) : "f"(x));
    return r;
}
__device__ __forceinline__ void mma_tf32(float c[4], const uint32_t a[4], const uint32_t b[2]) {
    asm("mma.sync.aligned.m16n8k8.row.col.f32.tf32.tf32.f32 "
        "{%0,%1,%2,%3}, {%4,%5,%6,%7}, {%8,%9}, {%0,%1,%2,%3};"
        : "+f"(c[0]), "+f"(c[1]), "+f"(c[2]), "+f"(c[3])
        : "r"(a[0]), "r"(a[1]), "r"(a[2]), "r"(a[3]), "r"(b[0]), "r"(b[1]));
}

// ---------------------------------------------------------------------------
// TF32 MMA GEMM with register-prefetch double buffering.
//   C[M,Ncols] = A[M,K] @ B[Ncols,K]^T
//   MODE 0: C = v (+bias)(+relu)
//   MODE 1: gc<D: xws bf16x2 = dinv*v -> Cb ; else z -> C2
//   MODE 2: gc<D: xws f32    = dinv*v -> C  ; else z -> C2
// ---------------------------------------------------------------------------
template<int BN, int WN, int MODE, bool RELU, bool HASB>
__global__ __launch_bounds__(256) void
k_mma(const float* __restrict__ A, const float* __restrict__ B,
      const float* __restrict__ bias,
      float* __restrict__ C, float* __restrict__ C2,
      uint32_t* __restrict__ Cb,
      int M, int Ncols, int K, int D) {
    constexpr int BM = 128, BK = 32, BKP = BK + 4;
    constexpr int MT = 2, NT = WN / 8;
    constexpr int AL = (BM * BK / 4) / 256;
    constexpr int BL = (BN * BK / 4) / 256;
    __shared__ uint32_t As[BM][BKP];
    __shared__ uint32_t Bs[BN][BKP];

    const int tid  = threadIdx.x;
    const int warp = tid >> 5, lane = tid & 31;
    const int grp  = lane >> 2, qid = lane & 3;
    const int wm0  = (warp & 3) * 32;
    const int wn0  = (warp >> 2) * WN;
    const int row0 = blockIdx.y * BM;
    const int col0 = blockIdx.x * BN;

    const int ldr = tid >> 3;        // row within tile for this thread's loads
    const int ldc = (tid & 7) * 4;   // col within tile

    float acc[MT][NT][4];
#pragma unroll
    for (int i = 0; i < MT; i++)
#pragma unroll
        for (int j = 0; j < NT; j++)
#pragma unroll
            for (int q = 0; q < 4; q++) acc[i][j][q] = 0.0f;

    float4 pa[AL], pb[BL];

    // prefetch tile 0
#pragma unroll
    for (int u = 0; u < AL; u++) {
        int gr = row0 + ldr + u * 32;
        pa[u] = make_float4(0.f, 0.f, 0.f, 0.f);
        if (gr < M) pa[u] = *(const float4*)(A + (size_t)gr * K + ldc);
    }
#pragma unroll
    for (int u = 0; u < BL; u++)
        pb[u] = *(const float4*)(B + (size_t)(col0 + ldr + u * 32) * K + ldc);

    for (int k0 = 0; k0 < K; k0 += BK) {
        __syncthreads();  // previous tile's mma reads done
#pragma unroll
        for (int u = 0; u < AL; u++) {
            uint32_t* p = &As[ldr + u * 32][ldc];
            p[0] = f2tf(pa[u].x); p[1] = f2tf(pa[u].y); p[2] = f2tf(pa[u].z); p[3] = f2tf(pa[u].w);
        }
#pragma unroll
        for (int u = 0; u < BL; u++) {
            uint32_t* p = &Bs[ldr + u * 32][ldc];
            p[0] = f2tf(pb[u].x); p[1] = f2tf(pb[u].y); p[2] = f2tf(pb[u].z); p[3] = f2tf(pb[u].w);
        }
        __syncthreads();

        // prefetch next tile (overlaps with mma below)
        if (k0 + BK < K) {
            int kn = k0 + BK;
#pragma unroll
            for (int u = 0; u < AL; u++) {
                int gr = row0 + ldr + u * 32;
                pa[u] = make_float4(0.f, 0.f, 0.f, 0.f);
                if (gr < M) pa[u] = *(const float4*)(A + (size_t)gr * K + kn + ldc);
            }
#pragma unroll
            for (int u = 0; u < BL; u++)
                pb[u] = *(const float4*)(B + (size_t)(col0 + ldr + u * 32) * K + kn + ldc);
        }

#pragma unroll
        for (int kk = 0; kk < BK / 8; kk++) {
            const int kb = kk * 8;
            uint32_t af[MT][4], bf[NT][2];
#pragma unroll
            for (int i = 0; i < MT; i++) {
                int m = wm0 + i * 16 + grp;
                af[i][0] = As[m    ][kb + qid];
                af[i][1] = As[m + 8][kb + qid];
                af[i][2] = As[m    ][kb + qid + 4];
                af[i][3] = As[m + 8][kb + qid + 4];
            }
#pragma unroll
            for (int j = 0; j < NT; j++) {
                int n = wn0 + j * 8 + grp;
                bf[j][0] = Bs[n][kb + qid];
                bf[j][1] = Bs[n][kb + qid + 4];
            }
#pragma unroll
            for (int i = 0; i < MT; i++)
#pragma unroll
                for (int j = 0; j < NT; j++)
                    mma_tf32(acc[i][j], af[i], bf[j]);
        }
    }

#pragma unroll
    for (int i = 0; i < MT; i++) {
#pragma unroll
        for (int h = 0; h < 2; h++) {
            int gr = row0 + wm0 + i * 16 + grp + h * 8;
            if (gr >= M) continue;
            float di = (MODE != 0) ? g_dinv[gr] : 0.0f;
#pragma unroll
            for (int j = 0; j < NT; j++) {
                int gc = col0 + wn0 + j * 8 + 2 * qid;
                float v0 = acc[i][j][2 * h];
                float v1 = acc[i][j][2 * h + 1];
                if (MODE == 0) {
                    if (HASB) { v0 += bias[gc]; v1 += bias[gc + 1]; }
                    if (RELU) { v0 = fmaxf(v0, 0.f); v1 = fmaxf(v1, 0.f); }
                    *(float2*)(C + (size_t)gr * Ncols + gc) = make_float2(v0, v1);
                } else if (MODE == 1) {
                    if (gc < D) {
                        __nv_bfloat162 p = __float22bfloat162_rn(make_float2(di * v0, di * v1));
                        Cb[(size_t)gr * (D / 2) + gc / 2] = *reinterpret_cast<uint32_t*>(&p);
                    } else {
                        *(float2*)(C2 + (size_t)gr * D + gc - D) = make_float2(v0, v1);
                    }
                } else {
                    if (gc < D) *(float2*)(C  + (size_t)gr * D + gc) = make_float2(di * v0, di * v1);
                    else        *(float2*)(C2 + (size_t)gr * D + gc - D) = make_float2(v0, v1);
                }
            }
        }
    }
}

// ---------------------------------------------------------------------------
// Layer-1 CSR gather + fused Euler update (warp/node, lane = 4 cols, MLP=4)
// ---------------------------------------------------------------------------
__device__ __forceinline__ void acc_bf4(float& sx, float& sy, float& sz, float& sw, uint2 v) {
    __nv_bfloat162 q0 = *reinterpret_cast<__nv_bfloat162*>(&v.x);
    __nv_bfloat162 q1 = *reinterpret_cast<__nv_bfloat162*>(&v.y);
    float2 g0 = __bfloat1622float2(q0);
    float2 g1 = __bfloat1622float2(q1);
    sx += g0.x; sy += g0.y; sz += g1.x; sw += g1.y;
}

__global__ void k_gather1(const float* __restrict__ b1) {
    int n    = (blockIdx.x * blockDim.x + threadIdx.x) >> 5;
    int lane = threadIdx.x & 31;
    if (n >= N_NODES) return;

    const uint2* xb = (const uint2*)g_xw1b;
    int beg = g_off[n], end = g_off[n + 1];

    float sx, sy, sz, sw;
    { uint2 sv = xb[(size_t)n * 32 + lane];
      sx = sy = sz = sw = 0.0f;
      acc_bf4(sx, sy, sz, sw, sv); }

    for (int base = beg; base < end; base += 32) {
        int mye = base + lane;
        int r = (mye < end) ? g_csr[mye] : 0;
        int cnt = min(32, end - base);
        int j = 0;
        for (; j + 4 <= cnt; j += 4) {
            int r0 = __shfl_sync(0xffffffffu, r, j);
            int r1 = __shfl_sync(0xffffffffu, r, j + 1);
            int r2 = __shfl_sync(0xffffffffu, r, j + 2);
            int r3 = __shfl_sync(0xffffffffu, r, j + 3);
            uint2 v0 = xb[(size_t)r0 * 32 + lane];
            uint2 v1 = xb[(size_t)r1 * 32 + lane];
            uint2 v2 = xb[(size_t)r2 * 32 + lane];
            uint2 v3 = xb[(size_t)r3 * 32 + lane];
            acc_bf4(sx, sy, sz, sw, v0);
            acc_bf4(sx, sy, sz, sw, v1);
            acc_bf4(sx, sy, sz, sw, v2);
            acc_bf4(sx, sy, sz, sw, v3);
        }
        for (; j < cnt; j++) {
            int rr = __shfl_sync(0xffffffffu, r, j);
            acc_bf4(sx, sy, sz, sw, xb[(size_t)rr * 32 + lane]);
        }
    }

    float u = g_dinv[n];
    size_t i4 = (size_t)n * 32 + lane;
    float4 z = ((const float4*)g_z1)[i4];
    float4 b = ((const float4*)b1)[lane];
    float4 h = ((const float4*)g_h1)[i4];
    h.x += EPS_F * tanhf(z.x + u * sx + b.x);
    h.y += EPS_F * tanhf(z.y + u * sy + b.y);
    h.z += EPS_F * tanhf(z.z + u * sz + b.z);
    h.w += EPS_F * tanhf(z.w + u * sw + b.w);
    ((float4*)g_h1)[i4] = h;
}

// ---------------------------------------------------------------------------
// Layer-2 CSR gather + fused update + log_softmax (warp/node, lane = col, MLP=4)
// ---------------------------------------------------------------------------
__global__ void k_gather2(const float* __restrict__ b2, float* __restrict__ out) {
    int n    = (blockIdx.x * blockDim.x + threadIdx.x) >> 5;
    int lane = threadIdx.x & 31;
    if (n >= N_NODES) return;

    int beg = g_off[n], end = g_off[n + 1];
    size_t base = (size_t)n * CLS;
    float s = g_xw2[base + lane];

    for (int eb = beg; eb < end; eb += 32) {
        int mye = eb + lane;
        int r = (mye < end) ? g_csr[mye] : 0;
        int cnt = min(32, end - eb);
        int j = 0;
        for (; j + 4 <= cnt; j += 4) {
            int r0 = __shfl_sync(0xffffffffu, r, j);
            int r1 = __shfl_sync(0xffffffffu, r, j + 1);
            int r2 = __shfl_sync(0xffffffffu, r, j + 2);
            int r3 = __shfl_sync(0xffffffffu, r, j + 3);
            float a0 = g_xw2[(size_t)r0 * CLS + lane];
            float a1 = g_xw2[(size_t)r1 * CLS + lane];
            float a2 = g_xw2[(size_t)r2 * CLS + lane];
            float a3 = g_xw2[(size_t)r3 * CLS + lane];
            s += (a0 + a1) + (a2 + a3);
        }
        for (; j < cnt; j++) {
            int rr = __shfl_sync(0xffffffffu, r, j);
            s += g_xw2[(size_t)rr * CLS + lane];
        }
    }

    float u = g_dinv[n];
    float z = g_z2[base + lane] + u * s + b2[lane];
    float v = g_h2[base + lane] + EPS_F * tanhf(z);
    float m = v;
#pragma unroll
    for (int o = 16; o > 0; o >>= 1) m = fmaxf(m, __shfl_xor_sync(0xffffffffu, m, o));
    float ex = expf(v - m);
    float sum = ex;
#pragma unroll
    for (int o = 16; o > 0; o >>= 1) sum += __shfl_xor_sync(0xffffffffu, sum, o);
    out[base + lane] = v - m - logf(sum);
}

// ---------------------------------------------------------------------------
// Launch
// ---------------------------------------------------------------------------
extern "C" void kernel_launch(void* const* d_in, const int* in_sizes, int n_in,
                              void* d_out, int out_size) {
    const float* x      = (const float*)d_in[0];
    const float* lin1_w = (const float*)d_in[1];
    const float* lin1_b = (const float*)d_in[2];
    const float* lin2_w = (const float*)d_in[3];
    const float* lin2_b = (const float*)d_in[4];
    const float* W1     = (const float*)d_in[5];
    const float* phi1   = (const float*)d_in[6];
    const float* b1     = (const float*)d_in[7];
    const float* W2     = (const float*)d_in[8];
    const float* phi2   = (const float*)d_in[9];
    const float* b2     = (const float*)d_in[10];
    const int*   ei     = (const int*)d_in[11];
    int E = in_sizes[11] / 2;
    const int* erow = ei;
    const int* ecol = ei + E;
    float* out = (float*)d_out;

    float *p_h1, *p_z1, *p_h2, *p_xw2, *p_z2, *p_c1, *p_c2;
    uint32_t* p_xw1b;
    cudaGetSymbolAddress((void**)&p_h1,   g_h1);
    cudaGetSymbolAddress((void**)&p_xw1b, g_xw1b);
    cudaGetSymbolAddress((void**)&p_z1,   g_z1);
    cudaGetSymbolAddress((void**)&p_h2,   g_h2);
    cudaGetSymbolAddress((void**)&p_xw2,  g_xw2);
    cudaGetSymbolAddress((void**)&p_z2,   g_z2);
    cudaGetSymbolAddress((void**)&p_c1,   g_comb1);
    cudaGetSymbolAddress((void**)&p_c2,   g_comb2);

    const int TPB = 256;
    int mb128 = (N_NODES + 127) / 128;
    int scan_blocks = (N_NODES + 1023) / 1024;
    int warp_blocks = (N_NODES * 32 + TPB - 1) / TPB;

    // ---- CSR build + normalization ----
    k_deg0     <<<(N_NODES + TPB - 1) / TPB, TPB>>>();
    k_deg_accum<<<(E + TPB - 1) / TPB, TPB>>>(ecol, E);
    k_scan1    <<<scan_blocks, 1024>>>(N_NODES);
    k_scan2    <<<1, 128>>>(scan_blocks);
    k_scan3    <<<scan_blocks, 1024>>>(N_NODES);
    k_place    <<<(E + TPB - 1) / TPB, TPB>>>(erow, ecol, E);

    // ---- combined weights ----
    k_comb<<<(HID * HID + CLS * CLS + TPB - 1) / TPB, TPB>>>(W1, phi1, W2, phi2);

    // ---- h1 = relu(x @ lin1_w^T + lin1_b)   [N,128], single col-block ----
    k_mma<128, 64, 0, true, true>
        <<<dim3(1, mb128), 256>>>(x, lin1_w, lin1_b, p_h1, nullptr, nullptr, N_NODES, HID, F_IN, 0);

    // ---- (xws1_bf16 | z1) = h1 @ comb1^T   [N,256], two col-blocks ----
    k_mma<128, 64, 1, false, false>
        <<<dim3(2, mb128), 256>>>(p_h1, p_c1, nullptr, nullptr, p_z1, p_xw1b, N_NODES, 2 * HID, HID, HID);

    // ---- layer-1 gather + fused Euler update ----
    k_gather1<<<warp_blocks, TPB>>>(b1);

    // ---- h2 = h1 @ lin2_w^T + lin2_b   [N,32] ----
    k_mma<32, 16, 0, false, true>
        <<<dim3(1, mb128), 256>>>(p_h1, lin2_w, lin2_b, p_h2, nullptr, nullptr, N_NODES, CLS, HID, 0);

    // ---- (xws2 | z2) = h2 @ comb2^T   [N,64] ----
    k_mma<64, 32, 2, false, false>
        <<<dim3(1, mb128), 256>>>(p_h2, p_c2, nullptr, p_xw2, p_z2, nullptr, N_NODES, 2 * CLS, CLS, CLS);

    // ---- layer-2 gather + fused update + log_softmax ----
    k_gather2<<<warp_blocks, TPB>>>(b2, out);
}

// round 9
// speedup vs baseline: 4.2991x; 1.0320x over previous
#include <cuda_runtime.h>
#include <cuda_bf16.h>
#include <math.h>
#include <stdint.h>

#define N_NODES 100000
#define F_IN    256
#define HID     128
#define CLS     32
#define E_MAX   1600000
#define EPS_F   0.1f
#define GAMMA_F 0.1f

// ---------------------------------------------------------------------------
// Scratch (device globals -- no allocation allowed)
// ---------------------------------------------------------------------------
__device__ __align__(16) int      g_degi [N_NODES];
__device__ __align__(16) int      g_scan [N_NODES];
__device__ __align__(16) int      g_bsum [128];
__device__ __align__(16) int      g_off  [N_NODES + 1];
__device__ __align__(16) int      g_cur  [N_NODES];
__device__ __align__(16) int      g_csr  [E_MAX];
__device__ __align__(16) float    g_dinv [N_NODES];
__device__ __align__(16) float    g_h1   [(size_t)N_NODES * HID];
__device__ __align__(16) uint32_t g_xw1b [(size_t)N_NODES * HID / 2];
__device__ __align__(16) float    g_z1   [(size_t)N_NODES * HID];
__device__ __align__(16) float    g_h2   [(size_t)N_NODES * CLS];
__device__ __align__(16) uint32_t g_xw2b [(size_t)N_NODES * CLS / 2];
__device__ __align__(16) float    g_z2   [(size_t)N_NODES * CLS];
__device__ __align__(16) float    g_comb1[2 * HID * HID];
__device__ __align__(16) float    g_comb2[2 * CLS * CLS];

// ---------------------------------------------------------------------------
// Degree / CSR build
// ---------------------------------------------------------------------------
__global__ void k_deg0() {
    int i = blockIdx.x * blockDim.x + threadIdx.x;
    if (i < N_NODES) g_degi[i] = 0;
}
__global__ void k_deg_accum(const int* __restrict__ col, int E) {
    int e = blockIdx.x * blockDim.x + threadIdx.x;
    if (e < E) atomicAdd(&g_degi[col[e]], 1);
}
__global__ void k_scan1(int n) {
    __shared__ int sh[1024];
    int i = blockIdx.x * 1024 + threadIdx.x;
    int v = (i < n) ? g_degi[i] : 0;
    sh[threadIdx.x] = v;
    __syncthreads();
    for (int o = 1; o < 1024; o <<= 1) {
        int t = (threadIdx.x >= o) ? sh[threadIdx.x - o] : 0;
        __syncthreads();
        sh[threadIdx.x] += t;
        __syncthreads();
    }
    if (i < n) g_scan[i] = sh[threadIdx.x];
    if (threadIdx.x == 1023) g_bsum[blockIdx.x] = sh[1023];
}
__global__ void k_scan2(int nb) {
    __shared__ int sh[128];
    int v = (threadIdx.x < nb) ? g_bsum[threadIdx.x] : 0;
    sh[threadIdx.x] = v;
    __syncthreads();
    for (int o = 1; o < 128; o <<= 1) {
        int t = (threadIdx.x >= o) ? sh[threadIdx.x - o] : 0;
        __syncthreads();
        sh[threadIdx.x] += t;
        __syncthreads();
    }
    if (threadIdx.x < nb) g_bsum[threadIdx.x] = sh[threadIdx.x];
}
// scan finalize + dinv fused
__global__ void k_scan3(int n) {
    int i = blockIdx.x * 1024 + threadIdx.x;
    if (i >= n) return;
    int d = g_degi[i];
    int add = (blockIdx.x > 0) ? g_bsum[blockIdx.x - 1] : 0;
    int inc = g_scan[i] + add;
    int off = inc - d;
    g_off[i] = off;
    g_cur[i] = off;
    g_dinv[i] = rsqrtf((float)d + 1.0f);
    if (i == n - 1) g_off[n] = inc;
}
__global__ void k_place(const int* __restrict__ row, const int* __restrict__ col, int E) {
    int e = blockIdx.x * blockDim.x + threadIdx.x;
    if (e >= E) return;
    int c = col[e];
    int p = atomicAdd(&g_cur[c], 1);
    g_csr[p] = row[e];
}

// ---------------------------------------------------------------------------
// Combined weights (both layers in one kernel)
// ---------------------------------------------------------------------------
__global__ void k_comb(const float* __restrict__ W1, const float* __restrict__ phi1,
                       const float* __restrict__ W2, const float* __restrict__ phi2) {
    int i = blockIdx.x * blockDim.x + threadIdx.x;
    if (i < HID * HID) {
        int r = i / HID, c = i % HID;
        g_comb1[r * HID + c] = phi1[i];
        g_comb1[(HID + r) * HID + c] = W1[r * HID + c] - W1[c * HID + r] - ((r == c) ? GAMMA_F : 0.0f);
    } else if (i < HID * HID + CLS * CLS) {
        int j = i - HID * HID;
        int r = j / CLS, c = j % CLS;
        g_comb2[r * CLS + c] = phi2[j];
        g_comb2[(CLS + r) * CLS + c] = W2[r * CLS + c] - W2[c * CLS + r] - ((r == c) ? GAMMA_F : 0.0f);
    }
}

// ---------------------------------------------------------------------------
// TF32 helpers
// ---------------------------------------------------------------------------
__device__ __forceinline__ uint32_t f2tf(float x) {
    uint32_t r;
    asm("cvt.rna.tf32.f32 %0, %1;" : "=r"(r) : "f"(x));
    return r;
}
__device__ __forceinline__ void mma_tf32(float c[4], const uint32_t a[4], const uint32_t b[2]) {
    asm("mma.sync.aligned.m16n8k8.row.col.f32.tf32.tf32.f32 "
        "{%0,%1,%2,%3}, {%4,%5,%6,%7}, {%8,%9}, {%0,%1,%2,%3};"
        : "+f"(c[0]), "+f"(c[1]), "+f"(c[2]), "+f"(c[3])
        : "r"(a[0]), "r"(a[1]), "r"(a[2]), "r"(a[3]), "r"(b[0]), "r"(b[1]));
}

// ---------------------------------------------------------------------------
// TF32 MMA GEMM with register-prefetch double buffering.
//   MODE 0: C = v (+bias)(+relu)
//   MODE 1: gc<D: Cb (bf16x2) = dinv[gr]*v ; else C2 (z, f32) = v
// ---------------------------------------------------------------------------
template<int BN, int WN, int MODE, bool RELU, bool HASB>
__global__ __launch_bounds__(256) void
k_mma(const float* __restrict__ A, const float* __restrict__ B,
      const float* __restrict__ bias,
      float* __restrict__ C, float* __restrict__ C2,
      uint32_t* __restrict__ Cb,
      int M, int Ncols, int K, int D) {
    constexpr int BM = 128, BK = 32, BKP = BK + 4;
    constexpr int MT = 2, NT = WN / 8;
    constexpr int AL = (BM * BK / 4) / 256;
    constexpr int BL = (BN * BK / 4) / 256;
    __shared__ uint32_t As[BM][BKP];
    __shared__ uint32_t Bs[BN][BKP];

    const int tid  = threadIdx.x;
    const int warp = tid >> 5, lane = tid & 31;
    const int grp  = lane >> 2, qid = lane & 3;
    const int wm0  = (warp & 3) * 32;
    const int wn0  = (warp >> 2) * WN;
    const int row0 = blockIdx.y * BM;
    const int col0 = blockIdx.x * BN;

    const int ldr = tid >> 3;
    const int ldc = (tid & 7) * 4;

    float acc[MT][NT][4];
#pragma unroll
    for (int i = 0; i < MT; i++)
#pragma unroll
        for (int j = 0; j < NT; j++)
#pragma unroll
            for (int q = 0; q < 4; q++) acc[i][j][q] = 0.0f;

    float4 pa[AL], pb[BL];

#pragma unroll
    for (int u = 0; u < AL; u++) {
        int gr = row0 + ldr + u * 32;
        pa[u] = make_float4(0.f, 0.f, 0.f, 0.f);
        if (gr < M) pa[u] = *(const float4*)(A + (size_t)gr * K + ldc);
    }
#pragma unroll
    for (int u = 0; u < BL; u++)
        pb[u] = *(const float4*)(B + (size_t)(col0 + ldr + u * 32) * K + ldc);

    for (int k0 = 0; k0 < K; k0 += BK) {
        __syncthreads();
#pragma unroll
        for (int u = 0; u < AL; u++) {
            uint32_t* p = &As[ldr + u * 32][ldc];
            p[0] = f2tf(pa[u].x); p[1] = f2tf(pa[u].y); p[2] = f2tf(pa[u].z); p[3] = f2tf(pa[u].w);
        }
#pragma unroll
        for (int u = 0; u < BL; u++) {
            uint32_t* p = &Bs[ldr + u * 32][ldc];
            p[0] = f2tf(pb[u].x); p[1] = f2tf(pb[u].y); p[2] = f2tf(pb[u].z); p[3] = f2tf(pb[u].w);
        }
        __syncthreads();

        if (k0 + BK < K) {
            int kn = k0 + BK;
#pragma unroll
            for (int u = 0; u < AL; u++) {
                int gr = row0 + ldr + u * 32;
                pa[u] = make_float4(0.f, 0.f, 0.f, 0.f);
                if (gr < M) pa[u] = *(const float4*)(A + (size_t)gr * K + kn + ldc);
            }
#pragma unroll
            for (int u = 0; u < BL; u++)
                pb[u] = *(const float4*)(B + (size_t)(col0 + ldr + u * 32) * K + kn + ldc);
        }

#pragma unroll
        for (int kk = 0; kk < BK / 8; kk++) {
            const int kb = kk * 8;
            uint32_t af[MT][4], bf[NT][2];
#pragma unroll
            for (int i = 0; i < MT; i++) {
                int m = wm0 + i * 16 + grp;
                af[i][0] = As[m    ][kb + qid];
                af[i][1] = As[m + 8][kb + qid];
                af[i][2] = As[m    ][kb + qid + 4];
                af[i][3] = As[m + 8][kb + qid + 4];
            }
#pragma unroll
            for (int j = 0; j < NT; j++) {
                int n = wn0 + j * 8 + grp;
                bf[j][0] = Bs[n][kb + qid];
                bf[j][1] = Bs[n][kb + qid + 4];
            }
#pragma unroll
            for (int i = 0; i < MT; i++)
#pragma unroll
                for (int j = 0; j < NT; j++)
                    mma_tf32(acc[i][j], af[i], bf[j]);
        }
    }

#pragma unroll
    for (int i = 0; i < MT; i++) {
#pragma unroll
        for (int h = 0; h < 2; h++) {
            int gr = row0 + wm0 + i * 16 + grp + h * 8;
            if (gr >= M) continue;
            float di = (MODE != 0) ? g_dinv[gr] : 0.0f;
#pragma unroll
            for (int j = 0; j < NT; j++) {
                int gc = col0 + wn0 + j * 8 + 2 * qid;
                float v0 = acc[i][j][2 * h];
                float v1 = acc[i][j][2 * h + 1];
                if (MODE == 0) {
                    if (HASB) { v0 += bias[gc]; v1 += bias[gc + 1]; }
                    if (RELU) { v0 = fmaxf(v0, 0.f); v1 = fmaxf(v1, 0.f); }
                    *(float2*)(C + (size_t)gr * Ncols + gc) = make_float2(v0, v1);
                } else {
                    if (gc < D) {
                        __nv_bfloat162 p = __float22bfloat162_rn(make_float2(di * v0, di * v1));
                        Cb[(size_t)gr * (D / 2) + gc / 2] = *reinterpret_cast<uint32_t*>(&p);
                    } else {
                        *(float2*)(C2 + (size_t)gr * D + gc - D) = make_float2(v0, v1);
                    }
                }
            }
        }
    }
}

// ---------------------------------------------------------------------------
// Layer-1 CSR gather + fused Euler update (warp/node, lane = 4 cols, MLP=4)
// ---------------------------------------------------------------------------
__device__ __forceinline__ void acc_bf4(float& sx, float& sy, float& sz, float& sw, uint2 v) {
    __nv_bfloat162 q0 = *reinterpret_cast<__nv_bfloat162*>(&v.x);
    __nv_bfloat162 q1 = *reinterpret_cast<__nv_bfloat162*>(&v.y);
    float2 g0 = __bfloat1622float2(q0);
    float2 g1 = __bfloat1622float2(q1);
    sx += g0.x; sy += g0.y; sz += g1.x; sw += g1.y;
}

__global__ void k_gather1(const float* __restrict__ b1) {
    int n    = (blockIdx.x * blockDim.x + threadIdx.x) >> 5;
    int lane = threadIdx.x & 31;
    if (n >= N_NODES) return;

    const uint2* xb = (const uint2*)g_xw1b;
    int beg = g_off[n], end = g_off[n + 1];

    float sx, sy, sz, sw;
    { uint2 sv = xb[(size_t)n * 32 + lane];
      sx = sy = sz = sw = 0.0f;
      acc_bf4(sx, sy, sz, sw, sv); }

    for (int base = beg; base < end; base += 32) {
        int mye = base + lane;
        int r = (mye < end) ? g_csr[mye] : 0;
        int cnt = min(32, end - base);
        int j = 0;
        for (; j + 4 <= cnt; j += 4) {
            int r0 = __shfl_sync(0xffffffffu, r, j);
            int r1 = __shfl_sync(0xffffffffu, r, j + 1);
            int r2 = __shfl_sync(0xffffffffu, r, j + 2);
            int r3 = __shfl_sync(0xffffffffu, r, j + 3);
            uint2 v0 = xb[(size_t)r0 * 32 + lane];
            uint2 v1 = xb[(size_t)r1 * 32 + lane];
            uint2 v2 = xb[(size_t)r2 * 32 + lane];
            uint2 v3 = xb[(size_t)r3 * 32 + lane];
            acc_bf4(sx, sy, sz, sw, v0);
            acc_bf4(sx, sy, sz, sw, v1);
            acc_bf4(sx, sy, sz, sw, v2);
            acc_bf4(sx, sy, sz, sw, v3);
        }
        for (; j < cnt; j++) {
            int rr = __shfl_sync(0xffffffffu, r, j);
            acc_bf4(sx, sy, sz, sw, xb[(size_t)rr * 32 + lane]);
        }
    }

    float u = g_dinv[n];
    size_t i4 = (size_t)n * 32 + lane;
    float4 z = ((const float4*)g_z1)[i4];
    float4 b = ((const float4*)b1)[lane];
    float4 h = ((const float4*)g_h1)[i4];
    h.x += EPS_F * tanhf(z.x + u * sx + b.x);
    h.y += EPS_F * tanhf(z.y + u * sy + b.y);
    h.z += EPS_F * tanhf(z.z + u * sz + b.z);
    h.w += EPS_F * tanhf(z.w + u * sw + b.w);
    ((float4*)g_h1)[i4] = h;
}

// ---------------------------------------------------------------------------
// Layer-2 gather (bf16) + fused update + log_softmax
//   Half-warp per node: 16 lanes x 2 classes (bf16x2 per lane).
//   CRITICAL: width-16 shuffles use the half-warp's OWN 16-lane mask --
//   the two half-warps process different nodes and diverge.
// ---------------------------------------------------------------------------
__global__ void k_gather2(const float* __restrict__ b2, float* __restrict__ out) {
    int n = (blockIdx.x * blockDim.x + threadIdx.x) >> 4;
    int l = threadIdx.x & 15;
    if (n >= N_NODES) return;

    const unsigned hm = 0xffffu << (threadIdx.x & 16);  // own half-warp's lanes

    int beg = g_off[n], end = g_off[n + 1];

    float s0, s1;
    { uint32_t sv = g_xw2b[(size_t)n * 16 + l];
      __nv_bfloat162 sp = *reinterpret_cast<__nv_bfloat162*>(&sv);
      float2 sf = __bfloat1622float2(sp);
      s0 = sf.x; s1 = sf.y; }

    for (int base = beg; base < end; base += 16) {
        int mye = base + l;
        int r = (mye < end) ? g_csr[mye] : 0;
        int cnt = min(16, end - base);
        int j = 0;
        for (; j + 4 <= cnt; j += 4) {
            int r0 = __shfl_sync(hm, r, j,     16);
            int r1 = __shfl_sync(hm, r, j + 1, 16);
            int r2 = __shfl_sync(hm, r, j + 2, 16);
            int r3 = __shfl_sync(hm, r, j + 3, 16);
            uint32_t a0 = g_xw2b[(size_t)r0 * 16 + l];
            uint32_t a1 = g_xw2b[(size_t)r1 * 16 + l];
            uint32_t a2 = g_xw2b[(size_t)r2 * 16 + l];
            uint32_t a3 = g_xw2b[(size_t)r3 * 16 + l];
            float2 f0 = __bfloat1622float2(*reinterpret_cast<__nv_bfloat162*>(&a0));
            float2 f1 = __bfloat1622float2(*reinterpret_cast<__nv_bfloat162*>(&a1));
            float2 f2 = __bfloat1622float2(*reinterpret_cast<__nv_bfloat162*>(&a2));
            float2 f3 = __bfloat1622float2(*reinterpret_cast<__nv_bfloat162*>(&a3));
            s0 += (f0.x + f1.x) + (f2.x + f3.x);
            s1 += (f0.y + f1.y) + (f2.y + f3.y);
        }
        for (; j < cnt; j++) {
            int rr = __shfl_sync(hm, r, j, 16);
            uint32_t a = g_xw2b[(size_t)rr * 16 + l];
            float2 f = __bfloat1622float2(*reinterpret_cast<__nv_bfloat162*>(&a));
            s0 += f.x; s1 += f.y;
        }
    }

    float u = g_dinv[n];
    size_t base2 = (size_t)n * CLS + 2 * l;
    float2 z = *(const float2*)(g_z2 + base2);
    float2 h = *(const float2*)(g_h2 + base2);
    float2 b = *(const float2*)(b2 + 2 * l);
    float v0 = h.x + EPS_F * tanhf(z.x + u * s0 + b.x);
    float v1 = h.y + EPS_F * tanhf(z.y + u * s1 + b.y);
    float m = fmaxf(v0, v1);
#pragma unroll
    for (int o = 8; o > 0; o >>= 1) m = fmaxf(m, __shfl_xor_sync(hm, m, o, 16));
    float sum = expf(v0 - m) + expf(v1 - m);
#pragma unroll
    for (int o = 8; o > 0; o >>= 1) sum += __shfl_xor_sync(hm, sum, o, 16);
    float ls = logf(sum);
    *(float2*)(out + base2) = make_float2(v0 - m - ls, v1 - m - ls);
}

// ---------------------------------------------------------------------------
// Launch (single default stream -- serial, known-good structure)
// ---------------------------------------------------------------------------
extern "C" void kernel_launch(void* const* d_in, const int* in_sizes, int n_in,
                              void* d_out, int out_size) {
    const float* x      = (const float*)d_in[0];
    const float* lin1_w = (const float*)d_in[1];
    const float* lin1_b = (const float*)d_in[2];
    const float* lin2_w = (const float*)d_in[3];
    const float* lin2_b = (const float*)d_in[4];
    const float* W1     = (const float*)d_in[5];
    const float* phi1   = (const float*)d_in[6];
    const float* b1     = (const float*)d_in[7];
    const float* W2     = (const float*)d_in[8];
    const float* phi2   = (const float*)d_in[9];
    const float* b2     = (const float*)d_in[10];
    const int*   ei     = (const int*)d_in[11];
    int E = in_sizes[11] / 2;
    const int* erow = ei;
    const int* ecol = ei + E;
    float* out = (float*)d_out;

    float *p_h1, *p_z1, *p_h2, *p_z2, *p_c1, *p_c2;
    uint32_t *p_xw1b, *p_xw2b;
    cudaGetSymbolAddress((void**)&p_h1,   g_h1);
    cudaGetSymbolAddress((void**)&p_xw1b, g_xw1b);
    cudaGetSymbolAddress((void**)&p_z1,   g_z1);
    cudaGetSymbolAddress((void**)&p_h2,   g_h2);
    cudaGetSymbolAddress((void**)&p_xw2b, g_xw2b);
    cudaGetSymbolAddress((void**)&p_z2,   g_z2);
    cudaGetSymbolAddress((void**)&p_c1,   g_comb1);
    cudaGetSymbolAddress((void**)&p_c2,   g_comb2);

    const int TPB = 256;
    int mb128 = (N_NODES + 127) / 128;
    int scan_blocks = (N_NODES + 1023) / 1024;
    int warp_blocks  = (N_NODES * 32 + TPB - 1) / TPB;
    int hwarp_blocks = (N_NODES * 16 + TPB - 1) / TPB;

    // ---- CSR build + normalization ----
    k_deg0     <<<(N_NODES + TPB - 1) / TPB, TPB>>>();
    k_deg_accum<<<(E + TPB - 1) / TPB, TPB>>>(ecol, E);
    k_scan1    <<<scan_blocks, 1024>>>(N_NODES);
    k_scan2    <<<1, 128>>>(scan_blocks);
    k_scan3    <<<scan_blocks, 1024>>>(N_NODES);
    k_place    <<<(E + TPB - 1) / TPB, TPB>>>(erow, ecol, E);

    // ---- combined weights ----
    k_comb<<<(HID * HID + CLS * CLS + TPB - 1) / TPB, TPB>>>(W1, phi1, W2, phi2);

    // ---- h1 = relu(x @ lin1_w^T + lin1_b)   [N,128] ----
    k_mma<128, 64, 0, true, true>
        <<<dim3(1, mb128), 256>>>(x, lin1_w, lin1_b, p_h1, nullptr, nullptr, N_NODES, HID, F_IN, 0);

    // ---- (xws1_bf16 | z1) = h1 @ comb1^T   [N,256] ----
    k_mma<128, 64, 1, false, false>
        <<<dim3(2, mb128), 256>>>(p_h1, p_c1, nullptr, nullptr, p_z1, p_xw1b, N_NODES, 2 * HID, HID, HID);

    // ---- layer-1 gather + fused Euler update ----
    k_gather1<<<warp_blocks, TPB>>>(b1);

    // ---- h2 = h1 @ lin2_w^T + lin2_b   [N,32] ----
    k_mma<32, 16, 0, false, true>
        <<<dim3(1, mb128), 256>>>(p_h1, lin2_w, lin2_b, p_h2, nullptr, nullptr, N_NODES, CLS, HID, 0);

    // ---- (xws2_bf16 | z2) = h2 @ comb2^T   [N,64] ----
    k_mma<64, 32, 1, false, false>
        <<<dim3(1, mb128), 256>>>(p_h2, p_c2, nullptr, nullptr, p_z2, p_xw2b, N_NODES, 2 * CLS, CLS, CLS);

    // ---- layer-2 gather + fused update + log_softmax ----
    k_gather2<<<hwarp_blocks, TPB>>>(b2, out);
}